// round 2
// baseline (speedup 1.0000x reference)
#include <cuda_runtime.h>
#include <cstdint>

#define N_NODES 100000
#define N_EDGES 3200000
#define IN_F    256
#define OUT_F   128

// Scratch for support = X @ W  (51.2 MB) — static device global (no allocs allowed)
__device__ float g_support[(size_t)N_NODES * OUT_F];

// ---------------------------------------------------------------------------
// GEMM: S[M,128] = X[M,256] @ W[256,128]   fp32, tiled shared memory
// BM=64, BN=128, BK=32, 256 threads, 4x8 micro-tile per thread
// smem: As 8448 B + Bs 16384 B = 24832 B (< 48 KB static limit)
// ---------------------------------------------------------------------------
__global__ __launch_bounds__(256) void gemm_kernel(
    const float* __restrict__ X, const float* __restrict__ W,
    float* __restrict__ S)
{
    constexpr int BM = 64, BN = 128, BK = 32;
    __shared__ float As[BM][BK + 1];   // +1 pad: conflict-free column reads
    __shared__ float Bs[BK][BN];

    const int tid  = threadIdx.x;
    const int tx   = tid & 15;         // 0..15 -> 8 output cols each
    const int ty   = tid >> 4;         // 0..15 -> 4 output rows each
    const int row0 = blockIdx.x * BM;

    float acc[4][8];
#pragma unroll
    for (int i = 0; i < 4; ++i)
#pragma unroll
        for (int j = 0; j < 8; ++j) acc[i][j] = 0.f;

    for (int k0 = 0; k0 < IN_F; k0 += BK) {
        // Load A tile: 64 rows x 32 cols = 512 float4, 2 per thread
#pragma unroll
        for (int i = 0; i < 2; ++i) {
            int idx = tid + i * 256;
            int r   = idx >> 3;          // 0..63
            int c4  = idx & 7;           // 0..7 (float4 index within 32 cols)
            float4 v = make_float4(0.f, 0.f, 0.f, 0.f);
            if (row0 + r < N_NODES)
                v = *(const float4*)&X[(size_t)(row0 + r) * IN_F + k0 + c4 * 4];
            As[r][c4 * 4 + 0] = v.x;
            As[r][c4 * 4 + 1] = v.y;
            As[r][c4 * 4 + 2] = v.z;
            As[r][c4 * 4 + 3] = v.w;
        }
        // Load B tile: 32 rows x 128 cols = 1024 float4, 4 per thread
#pragma unroll
        for (int i = 0; i < 4; ++i) {
            int idx = tid + i * 256;
            int r   = idx >> 5;          // 0..31
            int c4  = idx & 31;          // 0..31
            float4 v = *(const float4*)&W[(size_t)(k0 + r) * BN + c4 * 4];
            *(float4*)&Bs[r][c4 * 4] = v;
        }
        __syncthreads();

#pragma unroll
        for (int k = 0; k < BK; ++k) {
            float a[4];
#pragma unroll
            for (int i = 0; i < 4; ++i) a[i] = As[ty * 4 + i][k];
            float4 b0 = *(const float4*)&Bs[k][tx * 8];
            float4 b1 = *(const float4*)&Bs[k][tx * 8 + 4];
#pragma unroll
            for (int i = 0; i < 4; ++i) {
                acc[i][0] += a[i] * b0.x;
                acc[i][1] += a[i] * b0.y;
                acc[i][2] += a[i] * b0.z;
                acc[i][3] += a[i] * b0.w;
                acc[i][4] += a[i] * b1.x;
                acc[i][5] += a[i] * b1.y;
                acc[i][6] += a[i] * b1.z;
                acc[i][7] += a[i] * b1.w;
            }
        }
        __syncthreads();
    }

#pragma unroll
    for (int i = 0; i < 4; ++i) {
        int m = row0 + ty * 4 + i;
        if (m < N_NODES) {
            float4 o0 = make_float4(acc[i][0], acc[i][1], acc[i][2], acc[i][3]);
            float4 o1 = make_float4(acc[i][4], acc[i][5], acc[i][6], acc[i][7]);
            *(float4*)&S[(size_t)m * OUT_F + tx * 8]     = o0;
            *(float4*)&S[(size_t)m * OUT_F + tx * 8 + 4] = o1;
        }
    }
}

// ---------------------------------------------------------------------------
// Init out with bias (accumulation target for atomics)
// ---------------------------------------------------------------------------
__global__ void init_out_kernel(float* __restrict__ out,
                                const float* __restrict__ bias)
{
    const size_t total = (size_t)N_NODES * OUT_F;
    size_t i = (size_t)blockIdx.x * blockDim.x + threadIdx.x;
    size_t stride = (size_t)gridDim.x * blockDim.x;
    for (; i < total; i += stride)
        out[i] = bias[i & (OUT_F - 1)];
}

// ---------------------------------------------------------------------------
// SpMM scatter: one warp per edge, one red.add.v4.f32 per lane (4 feats)
// ---------------------------------------------------------------------------
__global__ __launch_bounds__(256) void spmm_kernel(
    const int*   __restrict__ erow,
    const int*   __restrict__ ecol,
    const float* __restrict__ eval,
    const float* __restrict__ S,
    float*       __restrict__ out)
{
    const long long tid = (long long)blockIdx.x * blockDim.x + threadIdx.x;
    const long long e   = tid >> 5;          // edge index (warp)
    const int       c   = (int)(tid & 31);   // float4 chunk within 128 feats
    if (e >= N_EDGES) return;

    const int   r   = __ldg(&erow[e]);
    const int   col = __ldg(&ecol[e]);
    const float v   = __ldg(&eval[e]);

    const float4 s = *(const float4*)&S[(size_t)col * OUT_F + c * 4];
    float4 p = make_float4(s.x * v, s.y * v, s.z * v, s.w * v);

    float* dst = &out[(size_t)r * OUT_F + c * 4];
    asm volatile("red.global.add.v4.f32 [%0], {%1, %2, %3, %4};"
                 :: "l"(dst), "f"(p.x), "f"(p.y), "f"(p.z), "f"(p.w)
                 : "memory");
}

// ---------------------------------------------------------------------------
// Final ReLU in place
// ---------------------------------------------------------------------------
__global__ void relu_kernel(float* __restrict__ out)
{
    const size_t total = (size_t)N_NODES * OUT_F;
    size_t i = (size_t)blockIdx.x * blockDim.x + threadIdx.x;
    size_t stride = (size_t)gridDim.x * blockDim.x;
    for (; i < total; i += stride)
        out[i] = fmaxf(out[i], 0.f);
}

// ---------------------------------------------------------------------------
// Inputs (metadata order): x, edge_row, edge_col, edge_val, weight, bias
// ---------------------------------------------------------------------------
extern "C" void kernel_launch(void* const* d_in, const int* in_sizes, int n_in,
                              void* d_out, int out_size)
{
    const float* x     = (const float*)d_in[0];
    const int*   erow  = (const int*)  d_in[1];
    const int*   ecol  = (const int*)  d_in[2];
    const float* eval_ = (const float*)d_in[3];
    const float* w     = (const float*)d_in[4];
    const float* bias  = (const float*)d_in[5];
    float*       out   = (float*)d_out;

    float* support;
    cudaGetSymbolAddress((void**)&support, g_support);

    // 1) support = X @ W
    gemm_kernel<<<(N_NODES + 63) / 64, 256>>>(x, w, support);

    // 2) out = bias (broadcast)
    init_out_kernel<<<4096, 256>>>(out, bias);

    // 3) out += scatter-add over edges
    const long long threads_total = (long long)N_EDGES * 32;
    const int blocks = (int)((threads_total + 255) / 256);
    spmm_kernel<<<blocks, 256>>>(erow, ecol, eval_, support, out);

    // 4) out = relu(out)
    relu_kernel<<<4096, 256>>>(out);
}

// round 3
// speedup vs baseline: 1.5077x; 1.5077x over previous
#include <cuda_runtime.h>
#include <cstdint>

#define N_NODES 100000
#define N_EDGES 3200000
#define IN_F    256
#define OUT_F   128

// -------- device scratch (no allocs allowed) --------
__device__ float g_support[(size_t)N_NODES * OUT_F];   // X @ W
__device__ int2  g_edges[N_EDGES];                     // (col, val-bits) sorted by row
__device__ int   g_deg[N_NODES];
__device__ int   g_cursor[N_NODES];
__device__ int   g_offset[N_NODES + 1];
__device__ int   g_bsum[128];
__device__ int   g_boff[128];

// ---------------------------------------------------------------------------
// GEMM: S[M,128] = X[M,256] @ W[256,128]   fp32 SIMT, BM=64 BN=128 BK=32
// ---------------------------------------------------------------------------
__global__ __launch_bounds__(256) void gemm_kernel(
    const float* __restrict__ X, const float* __restrict__ W,
    float* __restrict__ S)
{
    constexpr int BM = 64, BN = 128, BK = 32;
    __shared__ float As[BM][BK + 1];
    __shared__ float Bs[BK][BN];

    const int tid  = threadIdx.x;
    const int tx   = tid & 15;
    const int ty   = tid >> 4;
    const int row0 = blockIdx.x * BM;

    float acc[4][8];
#pragma unroll
    for (int i = 0; i < 4; ++i)
#pragma unroll
        for (int j = 0; j < 8; ++j) acc[i][j] = 0.f;

    for (int k0 = 0; k0 < IN_F; k0 += BK) {
#pragma unroll
        for (int i = 0; i < 2; ++i) {
            int idx = tid + i * 256;
            int r   = idx >> 3;
            int c4  = idx & 7;
            float4 v = make_float4(0.f, 0.f, 0.f, 0.f);
            if (row0 + r < N_NODES)
                v = *(const float4*)&X[(size_t)(row0 + r) * IN_F + k0 + c4 * 4];
            As[r][c4 * 4 + 0] = v.x;
            As[r][c4 * 4 + 1] = v.y;
            As[r][c4 * 4 + 2] = v.z;
            As[r][c4 * 4 + 3] = v.w;
        }
#pragma unroll
        for (int i = 0; i < 4; ++i) {
            int idx = tid + i * 256;
            int r   = idx >> 5;
            int c4  = idx & 31;
            float4 v = *(const float4*)&W[(size_t)(k0 + r) * BN + c4 * 4];
            *(float4*)&Bs[r][c4 * 4] = v;
        }
        __syncthreads();

#pragma unroll
        for (int k = 0; k < BK; ++k) {
            float a[4];
#pragma unroll
            for (int i = 0; i < 4; ++i) a[i] = As[ty * 4 + i][k];
            float4 b0 = *(const float4*)&Bs[k][tx * 8];
            float4 b1 = *(const float4*)&Bs[k][tx * 8 + 4];
#pragma unroll
            for (int i = 0; i < 4; ++i) {
                acc[i][0] += a[i] * b0.x;  acc[i][1] += a[i] * b0.y;
                acc[i][2] += a[i] * b0.z;  acc[i][3] += a[i] * b0.w;
                acc[i][4] += a[i] * b1.x;  acc[i][5] += a[i] * b1.y;
                acc[i][6] += a[i] * b1.z;  acc[i][7] += a[i] * b1.w;
            }
        }
        __syncthreads();
    }

#pragma unroll
    for (int i = 0; i < 4; ++i) {
        int m = row0 + ty * 4 + i;
        if (m < N_NODES) {
            *(float4*)&S[(size_t)m * OUT_F + tx * 8] =
                make_float4(acc[i][0], acc[i][1], acc[i][2], acc[i][3]);
            *(float4*)&S[(size_t)m * OUT_F + tx * 8 + 4] =
                make_float4(acc[i][4], acc[i][5], acc[i][6], acc[i][7]);
        }
    }
}

// ---------------------------------------------------------------------------
// CSR build: zero -> histogram -> 3-step exclusive scan -> scatter
// ---------------------------------------------------------------------------
__global__ void zero_kernel(int* __restrict__ deg, int* __restrict__ cur)
{
    int i = blockIdx.x * blockDim.x + threadIdx.x;
    if (i < N_NODES) { deg[i] = 0; cur[i] = 0; }
}

__global__ void hist_kernel(const int* __restrict__ erow, int* __restrict__ deg)
{
    int e = blockIdx.x * blockDim.x + threadIdx.x;
    if (e < N_EDGES) atomicAdd(&deg[erow[e]], 1);
}

// block of 1024 threads scans 1024 degrees -> exclusive partials + block sums
__global__ __launch_bounds__(1024) void scan1_kernel(
    const int* __restrict__ deg, int* __restrict__ offset, int* __restrict__ bsum)
{
    __shared__ int buf[2][1024];
    const int t = threadIdx.x;
    const int i = blockIdx.x * 1024 + t;
    const int v = (i < N_NODES) ? deg[i] : 0;
    buf[0][t] = v;
    __syncthreads();
    int src = 0;
#pragma unroll
    for (int d = 1; d < 1024; d <<= 1) {
        int nv = buf[src][t] + (t >= d ? buf[src][t - d] : 0);
        buf[src ^ 1][t] = nv;
        src ^= 1;
        __syncthreads();
    }
    if (i < N_NODES) offset[i] = buf[src][t] - v;   // exclusive
    if (t == 1023)   bsum[blockIdx.x] = buf[src][1023];
}

// single block scans the (<=128) block sums -> exclusive block offsets
__global__ __launch_bounds__(128) void scan2_kernel(
    const int* __restrict__ bsum, int* __restrict__ boff, int nb)
{
    __shared__ int buf[2][128];
    const int t = threadIdx.x;
    const int v = (t < nb) ? bsum[t] : 0;
    buf[0][t] = v;
    __syncthreads();
    int src = 0;
#pragma unroll
    for (int d = 1; d < 128; d <<= 1) {
        int nv = buf[src][t] + (t >= d ? buf[src][t - d] : 0);
        buf[src ^ 1][t] = nv;
        src ^= 1;
        __syncthreads();
    }
    boff[t] = buf[src][t] - v;   // exclusive
}

__global__ void scan3_kernel(int* __restrict__ offset, const int* __restrict__ boff)
{
    int i = blockIdx.x * blockDim.x + threadIdx.x;
    if (i < N_NODES) offset[i] += boff[i >> 10];
    if (i == 0) offset[N_NODES] = N_EDGES;
}

__global__ void scatter_kernel(
    const int* __restrict__ erow, const int* __restrict__ ecol,
    const float* __restrict__ eval, const int* __restrict__ offset,
    int* __restrict__ cursor, int2* __restrict__ edges)
{
    int e = blockIdx.x * blockDim.x + threadIdx.x;
    if (e >= N_EDGES) return;
    int r   = erow[e];
    int pos = offset[r] + atomicAdd(&cursor[r], 1);
    edges[pos] = make_int2(ecol[e], __float_as_int(eval[e]));
}

// ---------------------------------------------------------------------------
// Gather: warp per node, lane owns 4 feats; fused bias + ReLU
// ---------------------------------------------------------------------------
__global__ __launch_bounds__(256) void gather_kernel(
    const int* __restrict__ offset, const int2* __restrict__ edges,
    const float* __restrict__ S, const float* __restrict__ bias,
    float* __restrict__ out)
{
    const int warp = threadIdx.x >> 5;
    const int lane = threadIdx.x & 31;
    const int n    = blockIdx.x * 8 + warp;
    if (n >= N_NODES) return;

    const int start = offset[n];
    const int end   = offset[n + 1];

    float4 acc = make_float4(0.f, 0.f, 0.f, 0.f);

    int e0 = start;
    // full groups of 32 edges
    for (; e0 + 32 <= end; e0 += 32) {
        int2 ed = edges[e0 + lane];
#pragma unroll
        for (int j = 0; j < 32; ++j) {
            int   c = __shfl_sync(0xffffffffu, ed.x, j);
            float v = __int_as_float(__shfl_sync(0xffffffffu, ed.y, j));
            const float4 s = *(const float4*)&S[(size_t)c * OUT_F + lane * 4];
            acc.x += s.x * v; acc.y += s.y * v;
            acc.z += s.z * v; acc.w += s.w * v;
        }
    }
    // tail
    if (e0 < end) {
        int idx = e0 + lane;
        int2 ed = (idx < end) ? edges[idx] : make_int2(0, 0);
        int cnt = end - e0;
        for (int j = 0; j < cnt; ++j) {
            int   c = __shfl_sync(0xffffffffu, ed.x, j);
            float v = __int_as_float(__shfl_sync(0xffffffffu, ed.y, j));
            const float4 s = *(const float4*)&S[(size_t)c * OUT_F + lane * 4];
            acc.x += s.x * v; acc.y += s.y * v;
            acc.z += s.z * v; acc.w += s.w * v;
        }
    }

    const float4 b = *(const float4*)&bias[lane * 4];
    float4 o;
    o.x = fmaxf(acc.x + b.x, 0.f);
    o.y = fmaxf(acc.y + b.y, 0.f);
    o.z = fmaxf(acc.z + b.z, 0.f);
    o.w = fmaxf(acc.w + b.w, 0.f);
    *(float4*)&out[(size_t)n * OUT_F + lane * 4] = o;
}

// ---------------------------------------------------------------------------
// Inputs (metadata order): x, edge_row, edge_col, edge_val, weight, bias
// ---------------------------------------------------------------------------
extern "C" void kernel_launch(void* const* d_in, const int* in_sizes, int n_in,
                              void* d_out, int out_size)
{
    const float* x     = (const float*)d_in[0];
    const int*   erow  = (const int*)  d_in[1];
    const int*   ecol  = (const int*)  d_in[2];
    const float* eval_ = (const float*)d_in[3];
    const float* w     = (const float*)d_in[4];
    const float* bias  = (const float*)d_in[5];
    float*       out   = (float*)d_out;

    float* support;  cudaGetSymbolAddress((void**)&support, g_support);
    int2*  edges;    cudaGetSymbolAddress((void**)&edges,   g_edges);
    int*   deg;      cudaGetSymbolAddress((void**)&deg,     g_deg);
    int*   cursor;   cudaGetSymbolAddress((void**)&cursor,  g_cursor);
    int*   offset;   cudaGetSymbolAddress((void**)&offset,  g_offset);
    int*   bsum;     cudaGetSymbolAddress((void**)&bsum,    g_bsum);
    int*   boff;     cudaGetSymbolAddress((void**)&boff,    g_boff);

    const int nb = (N_NODES + 1023) / 1024;   // 98 scan blocks

    // CSR build
    zero_kernel<<<(N_NODES + 255) / 256, 256>>>(deg, cursor);
    hist_kernel<<<(N_EDGES + 255) / 256, 256>>>(erow, deg);
    scan1_kernel<<<nb, 1024>>>(deg, offset, bsum);
    scan2_kernel<<<1, 128>>>(bsum, boff, nb);
    scan3_kernel<<<(N_NODES + 255) / 256, 256>>>(offset, boff);
    scatter_kernel<<<(N_EDGES + 255) / 256, 256>>>(erow, ecol, eval_, offset, cursor, edges);

    // support = X @ W
    gemm_kernel<<<(N_NODES + 63) / 64, 256>>>(x, w, support);

    // out = relu(A @ support + bias)
    gather_kernel<<<(N_NODES + 7) / 8, 256>>>(offset, edges, support, bias, out);
}

// round 6
// speedup vs baseline: 2.7179x; 1.8026x over previous
#include <cuda_runtime.h>
#include <cuda_bf16.h>
#include <cstdint>

#define N_NODES 100000
#define N_EDGES 3200000
#define IN_F    256
#define OUT_F   128

// -------- device scratch (no allocs allowed) --------
__device__ float g_support[(size_t)N_NODES * OUT_F];   // X @ W
__device__ int2  g_edges[N_EDGES];                     // (col, val-bits) sorted by row
__device__ int   g_deg[N_NODES];
__device__ int   g_cursor[N_NODES];
__device__ int   g_offset[N_NODES + 1];
__device__ int   g_bsum[128];
__device__ int   g_boff[128];
// W split to bf16 hi/lo, transposed to [n][k] (k contiguous) for mma B-col fragments
__device__ __align__(16) __nv_bfloat16 g_Bhi[OUT_F * IN_F];
__device__ __align__(16) __nv_bfloat16 g_Blo[OUT_F * IN_F];

// ---------------------------------------------------------------------------
// W -> split bf16 hi/lo, transposed [n][k]
// ---------------------------------------------------------------------------
__global__ void wconv_kernel(const float* __restrict__ W,
                             __nv_bfloat16* __restrict__ Bhi,
                             __nv_bfloat16* __restrict__ Blo)
{
    int idx = blockIdx.x * blockDim.x + threadIdx.x;   // k*128 + n
    if (idx >= IN_F * OUT_F) return;
    int k = idx >> 7;
    int n = idx & 127;
    float v = W[idx];
    __nv_bfloat16 h = __float2bfloat16(v);
    __nv_bfloat16 l = __float2bfloat16(v - __bfloat162float(h));
    Bhi[n * IN_F + k] = h;
    Blo[n * IN_F + k] = l;
}

// ---------------------------------------------------------------------------
// Split-bf16 GEMM via mma.sync m16n8k16 (plain sm_100-compatible HMMA path)
// CTA: 128 rows x 128 cols, 8 warps (warp tile 32x64), K chunks of 64.
// ---------------------------------------------------------------------------
#define ASTRIDE 72          // padded row stride (elements) for A/B smem tiles
#define TILE_BYTES (128 * ASTRIDE * 2)      // 18432
#define GEMM_SMEM  (4 * TILE_BYTES)         // 73728

__device__ __forceinline__ void mma_bf16(float* c, const uint32_t* a, const uint32_t* b)
{
    asm volatile(
        "mma.sync.aligned.m16n8k16.row.col.f32.bf16.bf16.f32 "
        "{%0,%1,%2,%3}, {%4,%5,%6,%7}, {%8,%9}, {%0,%1,%2,%3};\n"
        : "+f"(c[0]), "+f"(c[1]), "+f"(c[2]), "+f"(c[3])
        : "r"(a[0]), "r"(a[1]), "r"(a[2]), "r"(a[3]), "r"(b[0]), "r"(b[1]));
}

__global__ __launch_bounds__(256) void gemm_mma_kernel(
    const float* __restrict__ X,
    const __nv_bfloat16* __restrict__ Bhi,
    const __nv_bfloat16* __restrict__ Blo,
    float* __restrict__ S)
{
    extern __shared__ __align__(16) unsigned char smem[];
    __nv_bfloat16* Ah = (__nv_bfloat16*)(smem);
    __nv_bfloat16* Al = (__nv_bfloat16*)(smem + TILE_BYTES);
    __nv_bfloat16* Bh = (__nv_bfloat16*)(smem + 2 * TILE_BYTES);
    __nv_bfloat16* Bl = (__nv_bfloat16*)(smem + 3 * TILE_BYTES);

    const int tid  = threadIdx.x;
    const int wid  = tid >> 5;
    const int lane = tid & 31;
    const int g    = lane >> 2;      // group id 0..7
    const int tig  = lane & 3;       // thread-in-group
    const int row0 = blockIdx.x * 128;

    const int mrow0 = (wid & 3) * 32;   // warp row offset in CTA tile
    const int ncol0 = (wid >> 2) * 64;  // warp col offset

    float acc[2][8][4];
#pragma unroll
    for (int mi = 0; mi < 2; ++mi)
#pragma unroll
        for (int ni = 0; ni < 8; ++ni)
#pragma unroll
            for (int r = 0; r < 4; ++r) acc[mi][ni][r] = 0.f;

    for (int k0 = 0; k0 < IN_F; k0 += 64) {
        if (k0) __syncthreads();   // previous chunk's mma reads done

        // --- stage A: load X fp32, split into bf16 hi/lo ---
#pragma unroll
        for (int i = 0; i < 8; ++i) {
            int idx = tid + i * 256;         // 0..2047
            int row = idx >> 4;              // 0..127
            int c4  = (idx & 15) * 4;        // k within chunk, 0..60 step 4
            float4 v = make_float4(0.f, 0.f, 0.f, 0.f);
            int grow = row0 + row;
            if (grow < N_NODES)
                v = *(const float4*)&X[(size_t)grow * IN_F + k0 + c4];
            __nv_bfloat162 h01 = __floats2bfloat162_rn(v.x, v.y);
            __nv_bfloat162 h23 = __floats2bfloat162_rn(v.z, v.w);
            __nv_bfloat162 l01 = __floats2bfloat162_rn(v.x - __low2float(h01),
                                                       v.y - __high2float(h01));
            __nv_bfloat162 l23 = __floats2bfloat162_rn(v.z - __low2float(h23),
                                                       v.w - __high2float(h23));
            int off = row * ASTRIDE + c4;
            *(__nv_bfloat162*)&Ah[off]     = h01;
            *(__nv_bfloat162*)&Ah[off + 2] = h23;
            *(__nv_bfloat162*)&Al[off]     = l01;
            *(__nv_bfloat162*)&Al[off + 2] = l23;
        }
        // --- stage B: copy pre-split W chunk [n][k0..k0+63] ---
#pragma unroll
        for (int i = 0; i < 4; ++i) {
            int idx = tid + i * 256;         // 0..1023
            int n   = idx >> 3;              // 0..127
            int k8  = (idx & 7) * 8;         // 0..56 step 8
            uint4 vh = *(const uint4*)&Bhi[n * IN_F + k0 + k8];
            uint4 vl = *(const uint4*)&Blo[n * IN_F + k0 + k8];
            *(uint4*)&Bh[n * ASTRIDE + k8] = vh;
            *(uint4*)&Bl[n * ASTRIDE + k8] = vl;
        }
        __syncthreads();

        // --- compute: 4 k16-steps, 2 M tiles x 8 N tiles, 3 split products ---
#pragma unroll
        for (int kk = 0; kk < 4; ++kk) {
            const int kb = kk * 16;
            uint32_t ah[2][4], al[2][4];
#pragma unroll
            for (int mi = 0; mi < 2; ++mi) {
                int ra = (mrow0 + mi * 16 + g) * ASTRIDE + kb + 2 * tig;
                int rb = ra + 8 * ASTRIDE;
                ah[mi][0] = *(const uint32_t*)&Ah[ra];
                ah[mi][1] = *(const uint32_t*)&Ah[rb];
                ah[mi][2] = *(const uint32_t*)&Ah[ra + 8];
                ah[mi][3] = *(const uint32_t*)&Ah[rb + 8];
                al[mi][0] = *(const uint32_t*)&Al[ra];
                al[mi][1] = *(const uint32_t*)&Al[rb];
                al[mi][2] = *(const uint32_t*)&Al[ra + 8];
                al[mi][3] = *(const uint32_t*)&Al[rb + 8];
            }
#pragma unroll
            for (int ni = 0; ni < 8; ++ni) {
                int cb = (ncol0 + ni * 8 + g) * ASTRIDE + kb + 2 * tig;
                uint32_t bh[2], bl[2];
                bh[0] = *(const uint32_t*)&Bh[cb];
                bh[1] = *(const uint32_t*)&Bh[cb + 8];
                bl[0] = *(const uint32_t*)&Bl[cb];
                bl[1] = *(const uint32_t*)&Bl[cb + 8];
#pragma unroll
                for (int mi = 0; mi < 2; ++mi) {
                    mma_bf16(acc[mi][ni], ah[mi], bh);
                    mma_bf16(acc[mi][ni], ah[mi], bl);
                    mma_bf16(acc[mi][ni], al[mi], bh);
                }
            }
        }
    }

    // --- epilogue: store fp32 accumulators ---
#pragma unroll
    for (int mi = 0; mi < 2; ++mi) {
        int r0 = row0 + mrow0 + mi * 16 + g;
        int r1 = r0 + 8;
#pragma unroll
        for (int ni = 0; ni < 8; ++ni) {
            int col = ncol0 + ni * 8 + tig * 2;
            if (r0 < N_NODES)
                *(float2*)&S[(size_t)r0 * OUT_F + col] =
                    make_float2(acc[mi][ni][0], acc[mi][ni][1]);
            if (r1 < N_NODES)
                *(float2*)&S[(size_t)r1 * OUT_F + col] =
                    make_float2(acc[mi][ni][2], acc[mi][ni][3]);
        }
    }
}

// ---------------------------------------------------------------------------
// CSR build: zero -> histogram -> 3-step exclusive scan -> scatter
// ---------------------------------------------------------------------------
__global__ void zero_kernel(int* __restrict__ deg, int* __restrict__ cur)
{
    int i = blockIdx.x * blockDim.x + threadIdx.x;
    if (i < N_NODES) { deg[i] = 0; cur[i] = 0; }
}

__global__ void hist_kernel(const int* __restrict__ erow, int* __restrict__ deg)
{
    int e = blockIdx.x * blockDim.x + threadIdx.x;
    if (e < N_EDGES) atomicAdd(&deg[erow[e]], 1);
}

__global__ __launch_bounds__(1024) void scan1_kernel(
    const int* __restrict__ deg, int* __restrict__ offset, int* __restrict__ bsum)
{
    __shared__ int buf[2][1024];
    const int t = threadIdx.x;
    const int i = blockIdx.x * 1024 + t;
    const int v = (i < N_NODES) ? deg[i] : 0;
    buf[0][t] = v;
    __syncthreads();
    int src = 0;
#pragma unroll
    for (int d = 1; d < 1024; d <<= 1) {
        int nv = buf[src][t] + (t >= d ? buf[src][t - d] : 0);
        buf[src ^ 1][t] = nv;
        src ^= 1;
        __syncthreads();
    }
    if (i < N_NODES) offset[i] = buf[src][t] - v;
    if (t == 1023)   bsum[blockIdx.x] = buf[src][1023];
}

__global__ __launch_bounds__(128) void scan2_kernel(
    const int* __restrict__ bsum, int* __restrict__ boff, int nb)
{
    __shared__ int buf[2][128];
    const int t = threadIdx.x;
    const int v = (t < nb) ? bsum[t] : 0;
    buf[0][t] = v;
    __syncthreads();
    int src = 0;
#pragma unroll
    for (int d = 1; d < 128; d <<= 1) {
        int nv = buf[src][t] + (t >= d ? buf[src][t - d] : 0);
        buf[src ^ 1][t] = nv;
        src ^= 1;
        __syncthreads();
    }
    boff[t] = buf[src][t] - v;
}

__global__ void scan3_kernel(int* __restrict__ offset, const int* __restrict__ boff)
{
    int i = blockIdx.x * blockDim.x + threadIdx.x;
    if (i < N_NODES) offset[i] += boff[i >> 10];
    if (i == 0) offset[N_NODES] = N_EDGES;
}

__global__ void scatter_kernel(
    const int* __restrict__ erow, const int* __restrict__ ecol,
    const float* __restrict__ eval, const int* __restrict__ offset,
    int* __restrict__ cursor, int2* __restrict__ edges)
{
    int e = blockIdx.x * blockDim.x + threadIdx.x;
    if (e >= N_EDGES) return;
    int r   = erow[e];
    int pos = offset[r] + atomicAdd(&cursor[r], 1);
    edges[pos] = make_int2(ecol[e], __float_as_int(eval[e]));
}

// ---------------------------------------------------------------------------
// Gather: warp per node, lane owns 4 feats; fused bias + ReLU
// ---------------------------------------------------------------------------
__global__ __launch_bounds__(256) void gather_kernel(
    const int* __restrict__ offset, const int2* __restrict__ edges,
    const float* __restrict__ S, const float* __restrict__ bias,
    float* __restrict__ out)
{
    const int warp = threadIdx.x >> 5;
    const int lane = threadIdx.x & 31;
    const int n    = blockIdx.x * 8 + warp;
    if (n >= N_NODES) return;

    const int start = __ldg(&offset[n]);
    const int end   = __ldg(&offset[n + 1]);

    float4 acc = make_float4(0.f, 0.f, 0.f, 0.f);

    int e0 = start;
    for (; e0 + 32 <= end; e0 += 32) {
        int2 ed = __ldg(&edges[e0 + lane]);
#pragma unroll
        for (int j = 0; j < 32; ++j) {
            int   c = __shfl_sync(0xffffffffu, ed.x, j);
            float v = __int_as_float(__shfl_sync(0xffffffffu, ed.y, j));
            const float4 s = *(const float4*)&S[(size_t)c * OUT_F + lane * 4];
            acc.x += s.x * v; acc.y += s.y * v;
            acc.z += s.z * v; acc.w += s.w * v;
        }
    }
    if (e0 < end) {
        int idx = e0 + lane;
        int2 ed = (idx < end) ? __ldg(&edges[idx]) : make_int2(0, 0);
        int cnt = end - e0;
        for (int j = 0; j < cnt; ++j) {
            int   c = __shfl_sync(0xffffffffu, ed.x, j);
            float v = __int_as_float(__shfl_sync(0xffffffffu, ed.y, j));
            const float4 s = *(const float4*)&S[(size_t)c * OUT_F + lane * 4];
            acc.x += s.x * v; acc.y += s.y * v;
            acc.z += s.z * v; acc.w += s.w * v;
        }
    }

    const float4 b = *(const float4*)&bias[lane * 4];
    float4 o;
    o.x = fmaxf(acc.x + b.x, 0.f);
    o.y = fmaxf(acc.y + b.y, 0.f);
    o.z = fmaxf(acc.z + b.z, 0.f);
    o.w = fmaxf(acc.w + b.w, 0.f);
    *(float4*)&out[(size_t)n * OUT_F + lane * 4] = o;
}

// ---------------------------------------------------------------------------
// Inputs (metadata order): x, edge_row, edge_col, edge_val, weight, bias
// ---------------------------------------------------------------------------
extern "C" void kernel_launch(void* const* d_in, const int* in_sizes, int n_in,
                              void* d_out, int out_size)
{
    const float* x     = (const float*)d_in[0];
    const int*   erow  = (const int*)  d_in[1];
    const int*   ecol  = (const int*)  d_in[2];
    const float* eval_ = (const float*)d_in[3];
    const float* w     = (const float*)d_in[4];
    const float* bias  = (const float*)d_in[5];
    float*       out   = (float*)d_out;

    float* support;  cudaGetSymbolAddress((void**)&support, g_support);
    int2*  edges;    cudaGetSymbolAddress((void**)&edges,   g_edges);
    int*   deg;      cudaGetSymbolAddress((void**)&deg,     g_deg);
    int*   cursor;   cudaGetSymbolAddress((void**)&cursor,  g_cursor);
    int*   offset;   cudaGetSymbolAddress((void**)&offset,  g_offset);
    int*   bsum;     cudaGetSymbolAddress((void**)&bsum,    g_bsum);
    int*   boff;     cudaGetSymbolAddress((void**)&boff,    g_boff);
    __nv_bfloat16* bhi; cudaGetSymbolAddress((void**)&bhi,  g_Bhi);
    __nv_bfloat16* blo; cudaGetSymbolAddress((void**)&blo,  g_Blo);

    cudaFuncSetAttribute(gemm_mma_kernel,
                         cudaFuncAttributeMaxDynamicSharedMemorySize, GEMM_SMEM);

    const int nb = (N_NODES + 1023) / 1024;

    // W split/transpose (tiny)
    wconv_kernel<<<(IN_F * OUT_F + 255) / 256, 256>>>(w, bhi, blo);

    // CSR build
    zero_kernel<<<(N_NODES + 255) / 256, 256>>>(deg, cursor);
    hist_kernel<<<(N_EDGES + 255) / 256, 256>>>(erow, deg);
    scan1_kernel<<<nb, 1024>>>(deg, offset, bsum);
    scan2_kernel<<<1, 128>>>(bsum, boff, nb);
    scan3_kernel<<<(N_NODES + 255) / 256, 256>>>(offset, boff);
    scatter_kernel<<<(N_EDGES + 255) / 256, 256>>>(erow, ecol, eval_, offset, cursor, edges);

    // support = X @ W  (split-bf16 mma.sync)
    gemm_mma_kernel<<<(N_NODES + 127) / 128, 256, GEMM_SMEM>>>(x, bhi, blo, support);

    // out = relu(A @ support + bias)
    gather_kernel<<<(N_NODES + 7) / 8, 256>>>(offset, edges, support, bias, out);
}

// round 7
// speedup vs baseline: 3.0292x; 1.1145x over previous
#include <cuda_runtime.h>
#include <cuda_bf16.h>
#include <cuda_fp16.h>
#include <cstdint>

#define N_NODES 100000
#define N_EDGES 3200000
#define IN_F    256
#define OUT_F   128

// -------- device scratch (no allocs allowed) --------
__device__ __half g_support[(size_t)N_NODES * OUT_F];  // X @ W in fp16
__device__ int2  g_edges[N_EDGES];                     // (col, val-bits) sorted by row
__device__ int   g_deg[N_NODES];
__device__ int   g_cursor[N_NODES];
__device__ int   g_offset[N_NODES + 1];
__device__ int   g_bsum[128];
__device__ int   g_boff[128];
// W split to bf16 hi/lo, transposed to [n][k] (k contiguous) for mma B-col fragments
__device__ __align__(16) __nv_bfloat16 g_Bhi[OUT_F * IN_F];
__device__ __align__(16) __nv_bfloat16 g_Blo[OUT_F * IN_F];

// ---------------------------------------------------------------------------
// W -> split bf16 hi/lo, transposed [n][k]
// ---------------------------------------------------------------------------
__global__ void wconv_kernel(const float* __restrict__ W,
                             __nv_bfloat16* __restrict__ Bhi,
                             __nv_bfloat16* __restrict__ Blo)
{
    int idx = blockIdx.x * blockDim.x + threadIdx.x;   // k*128 + n
    if (idx >= IN_F * OUT_F) return;
    int k = idx >> 7;
    int n = idx & 127;
    float v = W[idx];
    __nv_bfloat16 h = __float2bfloat16(v);
    __nv_bfloat16 l = __float2bfloat16(v - __bfloat162float(h));
    Bhi[n * IN_F + k] = h;
    Blo[n * IN_F + k] = l;
}

// ---------------------------------------------------------------------------
// Split-bf16 GEMM via mma.sync m16n8k16; fp16 output for the gather stage
// CTA: 128 rows x 128 cols, 8 warps (warp tile 32x64), K chunks of 64.
// ---------------------------------------------------------------------------
#define ASTRIDE 72          // padded row stride (elements) for A/B smem tiles
#define TILE_BYTES (128 * ASTRIDE * 2)      // 18432
#define GEMM_SMEM  (4 * TILE_BYTES)         // 73728

__device__ __forceinline__ void mma_bf16(float* c, const uint32_t* a, const uint32_t* b)
{
    asm volatile(
        "mma.sync.aligned.m16n8k16.row.col.f32.bf16.bf16.f32 "
        "{%0,%1,%2,%3}, {%4,%5,%6,%7}, {%8,%9}, {%0,%1,%2,%3};\n"
        : "+f"(c[0]), "+f"(c[1]), "+f"(c[2]), "+f"(c[3])
        : "r"(a[0]), "r"(a[1]), "r"(a[2]), "r"(a[3]), "r"(b[0]), "r"(b[1]));
}

__global__ __launch_bounds__(256) void gemm_mma_kernel(
    const float* __restrict__ X,
    const __nv_bfloat16* __restrict__ Bhi,
    const __nv_bfloat16* __restrict__ Blo,
    __half* __restrict__ S)
{
    extern __shared__ __align__(16) unsigned char smem[];
    __nv_bfloat16* Ah = (__nv_bfloat16*)(smem);
    __nv_bfloat16* Al = (__nv_bfloat16*)(smem + TILE_BYTES);
    __nv_bfloat16* Bh = (__nv_bfloat16*)(smem + 2 * TILE_BYTES);
    __nv_bfloat16* Bl = (__nv_bfloat16*)(smem + 3 * TILE_BYTES);

    const int tid  = threadIdx.x;
    const int wid  = tid >> 5;
    const int lane = tid & 31;
    const int g    = lane >> 2;      // group id 0..7
    const int tig  = lane & 3;       // thread-in-group
    const int row0 = blockIdx.x * 128;

    const int mrow0 = (wid & 3) * 32;   // warp row offset in CTA tile
    const int ncol0 = (wid >> 2) * 64;  // warp col offset

    float acc[2][8][4];
#pragma unroll
    for (int mi = 0; mi < 2; ++mi)
#pragma unroll
        for (int ni = 0; ni < 8; ++ni)
#pragma unroll
            for (int r = 0; r < 4; ++r) acc[mi][ni][r] = 0.f;

    for (int k0 = 0; k0 < IN_F; k0 += 64) {
        if (k0) __syncthreads();   // previous chunk's mma reads done

        // --- stage A: load X fp32, split into bf16 hi/lo ---
#pragma unroll
        for (int i = 0; i < 8; ++i) {
            int idx = tid + i * 256;         // 0..2047
            int row = idx >> 4;              // 0..127
            int c4  = (idx & 15) * 4;        // k within chunk, 0..60 step 4
            float4 v = make_float4(0.f, 0.f, 0.f, 0.f);
            int grow = row0 + row;
            if (grow < N_NODES)
                v = *(const float4*)&X[(size_t)grow * IN_F + k0 + c4];
            __nv_bfloat162 h01 = __floats2bfloat162_rn(v.x, v.y);
            __nv_bfloat162 h23 = __floats2bfloat162_rn(v.z, v.w);
            __nv_bfloat162 l01 = __floats2bfloat162_rn(v.x - __low2float(h01),
                                                       v.y - __high2float(h01));
            __nv_bfloat162 l23 = __floats2bfloat162_rn(v.z - __low2float(h23),
                                                       v.w - __high2float(h23));
            int off = row * ASTRIDE + c4;
            *(__nv_bfloat162*)&Ah[off]     = h01;
            *(__nv_bfloat162*)&Ah[off + 2] = h23;
            *(__nv_bfloat162*)&Al[off]     = l01;
            *(__nv_bfloat162*)&Al[off + 2] = l23;
        }
        // --- stage B: copy pre-split W chunk [n][k0..k0+63] ---
#pragma unroll
        for (int i = 0; i < 4; ++i) {
            int idx = tid + i * 256;         // 0..1023
            int n   = idx >> 3;              // 0..127
            int k8  = (idx & 7) * 8;         // 0..56 step 8
            uint4 vh = *(const uint4*)&Bhi[n * IN_F + k0 + k8];
            uint4 vl = *(const uint4*)&Blo[n * IN_F + k0 + k8];
            *(uint4*)&Bh[n * ASTRIDE + k8] = vh;
            *(uint4*)&Bl[n * ASTRIDE + k8] = vl;
        }
        __syncthreads();

        // --- compute: 4 k16-steps, 2 M tiles x 8 N tiles, 3 split products ---
#pragma unroll
        for (int kk = 0; kk < 4; ++kk) {
            const int kb = kk * 16;
            uint32_t ah[2][4], al[2][4];
#pragma unroll
            for (int mi = 0; mi < 2; ++mi) {
                int ra = (mrow0 + mi * 16 + g) * ASTRIDE + kb + 2 * tig;
                int rb = ra + 8 * ASTRIDE;
                ah[mi][0] = *(const uint32_t*)&Ah[ra];
                ah[mi][1] = *(const uint32_t*)&Ah[rb];
                ah[mi][2] = *(const uint32_t*)&Ah[ra + 8];
                ah[mi][3] = *(const uint32_t*)&Ah[rb + 8];
                al[mi][0] = *(const uint32_t*)&Al[ra];
                al[mi][1] = *(const uint32_t*)&Al[rb];
                al[mi][2] = *(const uint32_t*)&Al[ra + 8];
                al[mi][3] = *(const uint32_t*)&Al[rb + 8];
            }
#pragma unroll
            for (int ni = 0; ni < 8; ++ni) {
                int cb = (ncol0 + ni * 8 + g) * ASTRIDE + kb + 2 * tig;
                uint32_t bh[2], bl[2];
                bh[0] = *(const uint32_t*)&Bh[cb];
                bh[1] = *(const uint32_t*)&Bh[cb + 8];
                bl[0] = *(const uint32_t*)&Bl[cb];
                bl[1] = *(const uint32_t*)&Bl[cb + 8];
#pragma unroll
                for (int mi = 0; mi < 2; ++mi) {
                    mma_bf16(acc[mi][ni], ah[mi], bh);
                    mma_bf16(acc[mi][ni], ah[mi], bl);
                    mma_bf16(acc[mi][ni], al[mi], bh);
                }
            }
        }
    }

    // --- epilogue: store fp16 ---
#pragma unroll
    for (int mi = 0; mi < 2; ++mi) {
        int r0 = row0 + mrow0 + mi * 16 + g;
        int r1 = r0 + 8;
#pragma unroll
        for (int ni = 0; ni < 8; ++ni) {
            int col = ncol0 + ni * 8 + tig * 2;
            if (r0 < N_NODES)
                *(__half2*)&S[(size_t)r0 * OUT_F + col] =
                    __floats2half2_rn(acc[mi][ni][0], acc[mi][ni][1]);
            if (r1 < N_NODES)
                *(__half2*)&S[(size_t)r1 * OUT_F + col] =
                    __floats2half2_rn(acc[mi][ni][2], acc[mi][ni][3]);
        }
    }
}

// ---------------------------------------------------------------------------
// CSR build: zero -> histogram -> 3-step exclusive scan -> scatter
// ---------------------------------------------------------------------------
__global__ void zero_kernel(int* __restrict__ deg, int* __restrict__ cur)
{
    int i = blockIdx.x * blockDim.x + threadIdx.x;
    if (i < N_NODES) { deg[i] = 0; cur[i] = 0; }
}

__global__ void hist_kernel(const int* __restrict__ erow, int* __restrict__ deg)
{
    int e = blockIdx.x * blockDim.x + threadIdx.x;
    if (e < N_EDGES) atomicAdd(&deg[erow[e]], 1);
}

__global__ __launch_bounds__(1024) void scan1_kernel(
    const int* __restrict__ deg, int* __restrict__ offset, int* __restrict__ bsum)
{
    __shared__ int buf[2][1024];
    const int t = threadIdx.x;
    const int i = blockIdx.x * 1024 + t;
    const int v = (i < N_NODES) ? deg[i] : 0;
    buf[0][t] = v;
    __syncthreads();
    int src = 0;
#pragma unroll
    for (int d = 1; d < 1024; d <<= 1) {
        int nv = buf[src][t] + (t >= d ? buf[src][t - d] : 0);
        buf[src ^ 1][t] = nv;
        src ^= 1;
        __syncthreads();
    }
    if (i < N_NODES) offset[i] = buf[src][t] - v;
    if (t == 1023)   bsum[blockIdx.x] = buf[src][1023];
}

__global__ __launch_bounds__(128) void scan2_kernel(
    const int* __restrict__ bsum, int* __restrict__ boff, int nb)
{
    __shared__ int buf[2][128];
    const int t = threadIdx.x;
    const int v = (t < nb) ? bsum[t] : 0;
    buf[0][t] = v;
    __syncthreads();
    int src = 0;
#pragma unroll
    for (int d = 1; d < 128; d <<= 1) {
        int nv = buf[src][t] + (t >= d ? buf[src][t - d] : 0);
        buf[src ^ 1][t] = nv;
        src ^= 1;
        __syncthreads();
    }
    boff[t] = buf[src][t] - v;
}

__global__ void scan3_kernel(int* __restrict__ offset, const int* __restrict__ boff)
{
    int i = blockIdx.x * blockDim.x + threadIdx.x;
    if (i < N_NODES) offset[i] += boff[i >> 10];
    if (i == 0) offset[N_NODES] = N_EDGES;
}

__global__ void scatter_kernel(
    const int* __restrict__ erow, const int* __restrict__ ecol,
    const float* __restrict__ eval, const int* __restrict__ offset,
    int* __restrict__ cursor, int2* __restrict__ edges)
{
    int e = blockIdx.x * blockDim.x + threadIdx.x;
    if (e >= N_EDGES) return;
    int r   = erow[e];
    int pos = offset[r] + atomicAdd(&cursor[r], 1);
    edges[pos] = make_int2(ecol[e], __float_as_int(eval[e]));
}

// ---------------------------------------------------------------------------
// Gather: warp per node, lane owns 4 feats (fp16 support); fused bias + ReLU
// ---------------------------------------------------------------------------
__global__ __launch_bounds__(256) void gather_kernel(
    const int* __restrict__ offset, const int2* __restrict__ edges,
    const __half* __restrict__ S, const float* __restrict__ bias,
    float* __restrict__ out)
{
    const int warp = threadIdx.x >> 5;
    const int lane = threadIdx.x & 31;
    const int n    = blockIdx.x * 8 + warp;
    if (n >= N_NODES) return;

    const int start = __ldg(&offset[n]);
    const int end   = __ldg(&offset[n + 1]);

    float4 acc = make_float4(0.f, 0.f, 0.f, 0.f);

    int e0 = start;
    for (; e0 + 32 <= end; e0 += 32) {
        int2 ed = __ldg(&edges[e0 + lane]);
#pragma unroll
        for (int j = 0; j < 32; ++j) {
            int   c = __shfl_sync(0xffffffffu, ed.x, j);
            float v = __int_as_float(__shfl_sync(0xffffffffu, ed.y, j));
            const __half2* sp = (const __half2*)&S[(size_t)c * OUT_F + lane * 4];
            float2 s01 = __half22float2(sp[0]);
            float2 s23 = __half22float2(sp[1]);
            acc.x += s01.x * v; acc.y += s01.y * v;
            acc.z += s23.x * v; acc.w += s23.y * v;
        }
    }
    if (e0 < end) {
        int idx = e0 + lane;
        int2 ed = (idx < end) ? __ldg(&edges[idx]) : make_int2(0, 0);
        int cnt = end - e0;
        for (int j = 0; j < cnt; ++j) {
            int   c = __shfl_sync(0xffffffffu, ed.x, j);
            float v = __int_as_float(__shfl_sync(0xffffffffu, ed.y, j));
            const __half2* sp = (const __half2*)&S[(size_t)c * OUT_F + lane * 4];
            float2 s01 = __half22float2(sp[0]);
            float2 s23 = __half22float2(sp[1]);
            acc.x += s01.x * v; acc.y += s01.y * v;
            acc.z += s23.x * v; acc.w += s23.y * v;
        }
    }

    const float4 b = *(const float4*)&bias[lane * 4];
    float4 o;
    o.x = fmaxf(acc.x + b.x, 0.f);
    o.y = fmaxf(acc.y + b.y, 0.f);
    o.z = fmaxf(acc.z + b.z, 0.f);
    o.w = fmaxf(acc.w + b.w, 0.f);
    *(float4*)&out[(size_t)n * OUT_F + lane * 4] = o;
}

// ---------------------------------------------------------------------------
// Inputs (metadata order): x, edge_row, edge_col, edge_val, weight, bias
// ---------------------------------------------------------------------------
extern "C" void kernel_launch(void* const* d_in, const int* in_sizes, int n_in,
                              void* d_out, int out_size)
{
    const float* x     = (const float*)d_in[0];
    const int*   erow  = (const int*)  d_in[1];
    const int*   ecol  = (const int*)  d_in[2];
    const float* eval_ = (const float*)d_in[3];
    const float* w     = (const float*)d_in[4];
    const float* bias  = (const float*)d_in[5];
    float*       out   = (float*)d_out;

    __half* support; cudaGetSymbolAddress((void**)&support, g_support);
    int2*  edges;    cudaGetSymbolAddress((void**)&edges,   g_edges);
    int*   deg;      cudaGetSymbolAddress((void**)&deg,     g_deg);
    int*   cursor;   cudaGetSymbolAddress((void**)&cursor,  g_cursor);
    int*   offset;   cudaGetSymbolAddress((void**)&offset,  g_offset);
    int*   bsum;     cudaGetSymbolAddress((void**)&bsum,    g_bsum);
    int*   boff;     cudaGetSymbolAddress((void**)&boff,    g_boff);
    __nv_bfloat16* bhi; cudaGetSymbolAddress((void**)&bhi,  g_Bhi);
    __nv_bfloat16* blo; cudaGetSymbolAddress((void**)&blo,  g_Blo);

    cudaFuncSetAttribute(gemm_mma_kernel,
                         cudaFuncAttributeMaxDynamicSharedMemorySize, GEMM_SMEM);

    const int nb = (N_NODES + 1023) / 1024;

    // W split/transpose (tiny)
    wconv_kernel<<<(IN_F * OUT_F + 255) / 256, 256>>>(w, bhi, blo);

    // CSR build
    zero_kernel<<<(N_NODES + 255) / 256, 256>>>(deg, cursor);
    hist_kernel<<<(N_EDGES + 255) / 256, 256>>>(erow, deg);
    scan1_kernel<<<nb, 1024>>>(deg, offset, bsum);
    scan2_kernel<<<1, 128>>>(bsum, boff, nb);
    scan3_kernel<<<(N_NODES + 255) / 256, 256>>>(offset, boff);
    scatter_kernel<<<(N_EDGES + 255) / 256, 256>>>(erow, ecol, eval_, offset, cursor, edges);

    // support = X @ W  (split-bf16 mma.sync, fp16 out)
    gemm_mma_kernel<<<(N_NODES + 127) / 128, 256, GEMM_SMEM>>>(x, bhi, blo, support);

    // out = relu(A @ support + bias)
    gather_kernel<<<(N_NODES + 7) / 8, 256>>>(offset, edges, support, bias, out);
}

// round 9
// speedup vs baseline: 3.4587x; 1.1418x over previous
#include <cuda_runtime.h>
#include <cuda_fp16.h>
#include <cstdint>

#define N_NODES 100000
#define N_EDGES 3200000
#define IN_F    256
#define OUT_F   128

// -------- device scratch (no allocs allowed) --------
__device__ __half g_support[(size_t)N_NODES * OUT_F];  // X @ W in fp16
__device__ int2  g_edges[N_EDGES];                     // (col, val-bits) sorted by row
__device__ int   g_deg[N_NODES];
__device__ int   g_cursor[N_NODES];
__device__ int   g_offset[N_NODES + 1];
__device__ int   g_bsum[128];
__device__ int   g_boff[128];
// W in fp16, transposed to [n][k] (k contiguous) for mma B-col fragments
__device__ __align__(16) __half g_Bh[OUT_F * IN_F];

// ---------------------------------------------------------------------------
// W -> fp16, transposed [n][k]
// ---------------------------------------------------------------------------
__global__ void wconv_kernel(const float* __restrict__ W,
                             __half* __restrict__ Bh)
{
    int idx = blockIdx.x * blockDim.x + threadIdx.x;   // k*128 + n
    if (idx >= IN_F * OUT_F) return;
    int k = idx >> 7;
    int n = idx & 127;
    Bh[n * IN_F + k] = __float2half_rn(W[idx]);
}

// ---------------------------------------------------------------------------
// fp16 GEMM via mma.sync m16n8k16 (f32 accum); fp16 output for the gather
// CTA: 128 rows x 128 cols, 8 warps (warp tile 32x64), K chunks of 64.
// SMEM: 2 tiles x 18432 B = 36 KB static.
// ---------------------------------------------------------------------------
#define ASTRIDE 72          // padded row stride (elements) for A/B smem tiles

__device__ __forceinline__ void mma_f16(float* c, const uint32_t* a, const uint32_t* b)
{
    asm volatile(
        "mma.sync.aligned.m16n8k16.row.col.f32.f16.f16.f32 "
        "{%0,%1,%2,%3}, {%4,%5,%6,%7}, {%8,%9}, {%0,%1,%2,%3};\n"
        : "+f"(c[0]), "+f"(c[1]), "+f"(c[2]), "+f"(c[3])
        : "r"(a[0]), "r"(a[1]), "r"(a[2]), "r"(a[3]), "r"(b[0]), "r"(b[1]));
}

__global__ __launch_bounds__(256) void gemm_mma_kernel(
    const float* __restrict__ X,
    const __half* __restrict__ Bhg,
    __half* __restrict__ S)
{
    __shared__ __align__(16) __half Ah[128 * ASTRIDE];
    __shared__ __align__(16) __half Bh[128 * ASTRIDE];

    const int tid  = threadIdx.x;
    const int wid  = tid >> 5;
    const int lane = tid & 31;
    const int g    = lane >> 2;      // group id 0..7
    const int tig  = lane & 3;       // thread-in-group
    const int row0 = blockIdx.x * 128;

    const int mrow0 = (wid & 3) * 32;   // warp row offset in CTA tile
    const int ncol0 = (wid >> 2) * 64;  // warp col offset

    float acc[2][8][4];
#pragma unroll
    for (int mi = 0; mi < 2; ++mi)
#pragma unroll
        for (int ni = 0; ni < 8; ++ni)
#pragma unroll
            for (int r = 0; r < 4; ++r) acc[mi][ni][r] = 0.f;

    for (int k0 = 0; k0 < IN_F; k0 += 64) {
        if (k0) __syncthreads();   // previous chunk's mma reads done

        // --- stage A: load X fp32, convert fp16 ---
#pragma unroll
        for (int i = 0; i < 8; ++i) {
            int idx = tid + i * 256;         // 0..2047
            int row = idx >> 4;              // 0..127
            int c4  = (idx & 15) * 4;        // k within chunk, 0..60 step 4
            float4 v = make_float4(0.f, 0.f, 0.f, 0.f);
            int grow = row0 + row;
            if (grow < N_NODES)
                v = *(const float4*)&X[(size_t)grow * IN_F + k0 + c4];
            int off = row * ASTRIDE + c4;
            *(__half2*)&Ah[off]     = __floats2half2_rn(v.x, v.y);
            *(__half2*)&Ah[off + 2] = __floats2half2_rn(v.z, v.w);
        }
        // --- stage B: copy fp16 W chunk [n][k0..k0+63] ---
#pragma unroll
        for (int i = 0; i < 4; ++i) {
            int idx = tid + i * 256;         // 0..1023
            int n   = idx >> 3;              // 0..127
            int k8  = (idx & 7) * 8;         // 0..56 step 8
            uint4 vh = *(const uint4*)&Bhg[n * IN_F + k0 + k8];
            *(uint4*)&Bh[n * ASTRIDE + k8] = vh;
        }
        __syncthreads();

        // --- compute: 4 k16-steps, 2 M tiles x 8 N tiles ---
#pragma unroll
        for (int kk = 0; kk < 4; ++kk) {
            const int kb = kk * 16;
            uint32_t ah[2][4];
#pragma unroll
            for (int mi = 0; mi < 2; ++mi) {
                int ra = (mrow0 + mi * 16 + g) * ASTRIDE + kb + 2 * tig;
                int rb = ra + 8 * ASTRIDE;
                ah[mi][0] = *(const uint32_t*)&Ah[ra];
                ah[mi][1] = *(const uint32_t*)&Ah[rb];
                ah[mi][2] = *(const uint32_t*)&Ah[ra + 8];
                ah[mi][3] = *(const uint32_t*)&Ah[rb + 8];
            }
#pragma unroll
            for (int ni = 0; ni < 8; ++ni) {
                int cb = (ncol0 + ni * 8 + g) * ASTRIDE + kb + 2 * tig;
                uint32_t bh[2];
                bh[0] = *(const uint32_t*)&Bh[cb];
                bh[1] = *(const uint32_t*)&Bh[cb + 8];
#pragma unroll
                for (int mi = 0; mi < 2; ++mi)
                    mma_f16(acc[mi][ni], ah[mi], bh);
            }
        }
    }

    // --- epilogue: store fp16 ---
#pragma unroll
    for (int mi = 0; mi < 2; ++mi) {
        int r0 = row0 + mrow0 + mi * 16 + g;
        int r1 = r0 + 8;
#pragma unroll
        for (int ni = 0; ni < 8; ++ni) {
            int col = ncol0 + ni * 8 + tig * 2;
            if (r0 < N_NODES)
                *(__half2*)&S[(size_t)r0 * OUT_F + col] =
                    __floats2half2_rn(acc[mi][ni][0], acc[mi][ni][1]);
            if (r1 < N_NODES)
                *(__half2*)&S[(size_t)r1 * OUT_F + col] =
                    __floats2half2_rn(acc[mi][ni][2], acc[mi][ni][3]);
        }
    }
}

// ---------------------------------------------------------------------------
// CSR build: zero -> histogram -> 3-step exclusive scan -> scatter
// ---------------------------------------------------------------------------
__global__ void zero_kernel(int* __restrict__ deg, int* __restrict__ cur)
{
    int i = blockIdx.x * blockDim.x + threadIdx.x;
    if (i < N_NODES) { deg[i] = 0; cur[i] = 0; }
}

__global__ void hist_kernel(const int* __restrict__ erow, int* __restrict__ deg)
{
    int e = blockIdx.x * blockDim.x + threadIdx.x;
    if (e < N_EDGES) atomicAdd(&deg[erow[e]], 1);
}

__global__ __launch_bounds__(1024) void scan1_kernel(
    const int* __restrict__ deg, int* __restrict__ offset, int* __restrict__ bsum)
{
    __shared__ int buf[2][1024];
    const int t = threadIdx.x;
    const int i = blockIdx.x * 1024 + t;
    const int v = (i < N_NODES) ? deg[i] : 0;
    buf[0][t] = v;
    __syncthreads();
    int src = 0;
#pragma unroll
    for (int d = 1; d < 1024; d <<= 1) {
        int nv = buf[src][t] + (t >= d ? buf[src][t - d] : 0);
        buf[src ^ 1][t] = nv;
        src ^= 1;
        __syncthreads();
    }
    if (i < N_NODES) offset[i] = buf[src][t] - v;
    if (t == 1023)   bsum[blockIdx.x] = buf[src][1023];
}

__global__ __launch_bounds__(128) void scan2_kernel(
    const int* __restrict__ bsum, int* __restrict__ boff, int nb)
{
    __shared__ int buf[2][128];
    const int t = threadIdx.x;
    const int v = (t < nb) ? bsum[t] : 0;
    buf[0][t] = v;
    __syncthreads();
    int src = 0;
#pragma unroll
    for (int d = 1; d < 128; d <<= 1) {
        int nv = buf[src][t] + (t >= d ? buf[src][t - d] : 0);
        buf[src ^ 1][t] = nv;
        src ^= 1;
        __syncthreads();
    }
    boff[t] = buf[src][t] - v;
}

__global__ void scan3_kernel(int* __restrict__ offset, const int* __restrict__ boff)
{
    int i = blockIdx.x * blockDim.x + threadIdx.x;
    if (i < N_NODES) offset[i] += boff[i >> 10];
    if (i == 0) offset[N_NODES] = N_EDGES;
}

__global__ void scatter_kernel(
    const int* __restrict__ erow, const int* __restrict__ ecol,
    const float* __restrict__ eval, const int* __restrict__ offset,
    int* __restrict__ cursor, int2* __restrict__ edges)
{
    int e = blockIdx.x * blockDim.x + threadIdx.x;
    if (e >= N_EDGES) return;
    int r   = erow[e];
    int pos = offset[r] + atomicAdd(&cursor[r], 1);
    edges[pos] = make_int2(ecol[e], __float_as_int(eval[e]));
}

// ---------------------------------------------------------------------------
// Gather: warp per node, lane owns 4 feats (fp16 support); fused bias + ReLU
// ---------------------------------------------------------------------------
__global__ __launch_bounds__(256) void gather_kernel(
    const int* __restrict__ offset, const int2* __restrict__ edges,
    const __half* __restrict__ S, const float* __restrict__ bias,
    float* __restrict__ out)
{
    const int warp = threadIdx.x >> 5;
    const int lane = threadIdx.x & 31;
    const int n    = blockIdx.x * 8 + warp;
    if (n >= N_NODES) return;

    const int start = __ldg(&offset[n]);
    const int end   = __ldg(&offset[n + 1]);

    float4 acc = make_float4(0.f, 0.f, 0.f, 0.f);

    int e0 = start;
    for (; e0 + 32 <= end; e0 += 32) {
        int2 ed = __ldg(&edges[e0 + lane]);
#pragma unroll
        for (int j = 0; j < 32; ++j) {
            int   c = __shfl_sync(0xffffffffu, ed.x, j);
            float v = __int_as_float(__shfl_sync(0xffffffffu, ed.y, j));
            const __half2* sp = (const __half2*)&S[(size_t)c * OUT_F + lane * 4];
            float2 s01 = __half22float2(sp[0]);
            float2 s23 = __half22float2(sp[1]);
            acc.x += s01.x * v; acc.y += s01.y * v;
            acc.z += s23.x * v; acc.w += s23.y * v;
        }
    }
    if (e0 < end) {
        int idx = e0 + lane;
        int2 ed = (idx < end) ? __ldg(&edges[idx]) : make_int2(0, 0);
        int cnt = end - e0;
        for (int j = 0; j < cnt; ++j) {
            int   c = __shfl_sync(0xffffffffu, ed.x, j);
            float v = __int_as_float(__shfl_sync(0xffffffffu, ed.y, j));
            const __half2* sp = (const __half2*)&S[(size_t)c * OUT_F + lane * 4];
            float2 s01 = __half22float2(sp[0]);
            float2 s23 = __half22float2(sp[1]);
            acc.x += s01.x * v; acc.y += s01.y * v;
            acc.z += s23.x * v; acc.w += s23.y * v;
        }
    }

    const float4 b = *(const float4*)&bias[lane * 4];
    float4 o;
    o.x = fmaxf(acc.x + b.x, 0.f);
    o.y = fmaxf(acc.y + b.y, 0.f);
    o.z = fmaxf(acc.z + b.z, 0.f);
    o.w = fmaxf(acc.w + b.w, 0.f);
    *(float4*)&out[(size_t)n * OUT_F + lane * 4] = o;
}

// ---------------------------------------------------------------------------
// Inputs (metadata order): x, edge_row, edge_col, edge_val, weight, bias
// ---------------------------------------------------------------------------
extern "C" void kernel_launch(void* const* d_in, const int* in_sizes, int n_in,
                              void* d_out, int out_size)
{
    const float* x     = (const float*)d_in[0];
    const int*   erow  = (const int*)  d_in[1];
    const int*   ecol  = (const int*)  d_in[2];
    const float* eval_ = (const float*)d_in[3];
    const float* w     = (const float*)d_in[4];
    const float* bias  = (const float*)d_in[5];
    float*       out   = (float*)d_out;

    __half* support; cudaGetSymbolAddress((void**)&support, g_support);
    int2*  edges;    cudaGetSymbolAddress((void**)&edges,   g_edges);
    int*   deg;      cudaGetSymbolAddress((void**)&deg,     g_deg);
    int*   cursor;   cudaGetSymbolAddress((void**)&cursor,  g_cursor);
    int*   offset;   cudaGetSymbolAddress((void**)&offset,  g_offset);
    int*   bsum;     cudaGetSymbolAddress((void**)&bsum,    g_bsum);
    int*   boff;     cudaGetSymbolAddress((void**)&boff,    g_boff);
    __half* bh;      cudaGetSymbolAddress((void**)&bh,      g_Bh);

    const int nb = (N_NODES + 1023) / 1024;

    // W convert/transpose (tiny)
    wconv_kernel<<<(IN_F * OUT_F + 255) / 256, 256>>>(w, bh);

    // CSR build
    zero_kernel<<<(N_NODES + 255) / 256, 256>>>(deg, cursor);
    hist_kernel<<<(N_EDGES + 255) / 256, 256>>>(erow, deg);
    scan1_kernel<<<nb, 1024>>>(deg, offset, bsum);
    scan2_kernel<<<1, 128>>>(bsum, boff, nb);
    scan3_kernel<<<(N_NODES + 255) / 256, 256>>>(offset, boff);
    scatter_kernel<<<(N_EDGES + 255) / 256, 256>>>(erow, ecol, eval_, offset, cursor, edges);

    // support = X @ W  (fp16 mma.sync, fp32 accum, fp16 out)
    gemm_mma_kernel<<<(N_NODES + 127) / 128, 256>>>(x, bh, support);

    // out = relu(A @ support + bias)
    gather_kernel<<<(N_NODES + 7) / 8, 256>>>(offset, edges, support, bias, out);
}

// round 10
// speedup vs baseline: 3.5592x; 1.0291x over previous
#include <cuda_runtime.h>
#include <cuda_fp16.h>
#include <cstdint>

#define N_NODES 100000
#define N_EDGES 3200000
#define IN_F    256
#define OUT_F   128

// -------- device scratch (no allocs allowed) --------
__device__ __half g_support[(size_t)N_NODES * OUT_F];  // X @ W in fp16
__device__ int2  g_edges[N_EDGES];                     // (col, val-bits) sorted by row
__device__ int   g_deg[N_NODES];
__device__ int   g_cursor[N_NODES];
__device__ int   g_offset[N_NODES + 1];
__device__ int   g_bsum[128];
__device__ int   g_boff[128];
// W in fp16, transposed to [n][k] (k contiguous) for mma B-col fragments
__device__ __align__(16) __half g_Bh[OUT_F * IN_F];

// ---------------------------------------------------------------------------
// W -> fp16, transposed [n][k]
// ---------------------------------------------------------------------------
__global__ void wconv_kernel(const float* __restrict__ W,
                             __half* __restrict__ Bh)
{
    int idx = blockIdx.x * blockDim.x + threadIdx.x;   // k*128 + n
    if (idx >= IN_F * OUT_F) return;
    int k = idx >> 7;
    int n = idx & 127;
    Bh[n * IN_F + k] = __float2half_rn(W[idx]);
}

// ---------------------------------------------------------------------------
// fp16 GEMM via mma.sync m16n8k16 (f32 accum); fp16 output for the gather
// CTA: 128 rows x 128 cols, 8 warps (warp tile 32x64), K chunks of 64.
// SMEM: 2 tiles x 18432 B = 36 KB static.
// ---------------------------------------------------------------------------
#define ASTRIDE 72          // padded row stride (elements) for A/B smem tiles

__device__ __forceinline__ void mma_f16(float* c, const uint32_t* a, const uint32_t* b)
{
    asm volatile(
        "mma.sync.aligned.m16n8k16.row.col.f32.f16.f16.f32 "
        "{%0,%1,%2,%3}, {%4,%5,%6,%7}, {%8,%9}, {%0,%1,%2,%3};\n"
        : "+f"(c[0]), "+f"(c[1]), "+f"(c[2]), "+f"(c[3])
        : "r"(a[0]), "r"(a[1]), "r"(a[2]), "r"(a[3]), "r"(b[0]), "r"(b[1]));
}

__global__ __launch_bounds__(256) void gemm_mma_kernel(
    const float* __restrict__ X,
    const __half* __restrict__ Bhg,
    __half* __restrict__ S)
{
    __shared__ __align__(16) __half Ah[128 * ASTRIDE];
    __shared__ __align__(16) __half Bh[128 * ASTRIDE];

    const int tid  = threadIdx.x;
    const int wid  = tid >> 5;
    const int lane = tid & 31;
    const int g    = lane >> 2;      // group id 0..7
    const int tig  = lane & 3;       // thread-in-group
    const int row0 = blockIdx.x * 128;

    const int mrow0 = (wid & 3) * 32;   // warp row offset in CTA tile
    const int ncol0 = (wid >> 2) * 64;  // warp col offset

    float acc[2][8][4];
#pragma unroll
    for (int mi = 0; mi < 2; ++mi)
#pragma unroll
        for (int ni = 0; ni < 8; ++ni)
#pragma unroll
            for (int r = 0; r < 4; ++r) acc[mi][ni][r] = 0.f;

    for (int k0 = 0; k0 < IN_F; k0 += 64) {
        if (k0) __syncthreads();   // previous chunk's mma reads done

        // --- stage A: load X fp32, convert fp16 ---
#pragma unroll
        for (int i = 0; i < 8; ++i) {
            int idx = tid + i * 256;         // 0..2047
            int row = idx >> 4;              // 0..127
            int c4  = (idx & 15) * 4;        // k within chunk, 0..60 step 4
            float4 v = make_float4(0.f, 0.f, 0.f, 0.f);
            int grow = row0 + row;
            if (grow < N_NODES)
                v = *(const float4*)&X[(size_t)grow * IN_F + k0 + c4];
            int off = row * ASTRIDE + c4;
            *(__half2*)&Ah[off]     = __floats2half2_rn(v.x, v.y);
            *(__half2*)&Ah[off + 2] = __floats2half2_rn(v.z, v.w);
        }
        // --- stage B: copy fp16 W chunk [n][k0..k0+63] ---
#pragma unroll
        for (int i = 0; i < 4; ++i) {
            int idx = tid + i * 256;         // 0..1023
            int n   = idx >> 3;              // 0..127
            int k8  = (idx & 7) * 8;         // 0..56 step 8
            uint4 vh = *(const uint4*)&Bhg[n * IN_F + k0 + k8];
            *(uint4*)&Bh[n * ASTRIDE + k8] = vh;
        }
        __syncthreads();

        // --- compute: 4 k16-steps, 2 M tiles x 8 N tiles ---
#pragma unroll
        for (int kk = 0; kk < 4; ++kk) {
            const int kb = kk * 16;
            uint32_t ah[2][4];
#pragma unroll
            for (int mi = 0; mi < 2; ++mi) {
                int ra = (mrow0 + mi * 16 + g) * ASTRIDE + kb + 2 * tig;
                int rb = ra + 8 * ASTRIDE;
                ah[mi][0] = *(const uint32_t*)&Ah[ra];
                ah[mi][1] = *(const uint32_t*)&Ah[rb];
                ah[mi][2] = *(const uint32_t*)&Ah[ra + 8];
                ah[mi][3] = *(const uint32_t*)&Ah[rb + 8];
            }
#pragma unroll
            for (int ni = 0; ni < 8; ++ni) {
                int cb = (ncol0 + ni * 8 + g) * ASTRIDE + kb + 2 * tig;
                uint32_t bh[2];
                bh[0] = *(const uint32_t*)&Bh[cb];
                bh[1] = *(const uint32_t*)&Bh[cb + 8];
#pragma unroll
                for (int mi = 0; mi < 2; ++mi)
                    mma_f16(acc[mi][ni], ah[mi], bh);
            }
        }
    }

    // --- epilogue: store fp16 ---
#pragma unroll
    for (int mi = 0; mi < 2; ++mi) {
        int r0 = row0 + mrow0 + mi * 16 + g;
        int r1 = r0 + 8;
#pragma unroll
        for (int ni = 0; ni < 8; ++ni) {
            int col = ncol0 + ni * 8 + tig * 2;
            if (r0 < N_NODES)
                *(__half2*)&S[(size_t)r0 * OUT_F + col] =
                    __floats2half2_rn(acc[mi][ni][0], acc[mi][ni][1]);
            if (r1 < N_NODES)
                *(__half2*)&S[(size_t)r1 * OUT_F + col] =
                    __floats2half2_rn(acc[mi][ni][2], acc[mi][ni][3]);
        }
    }
}

// ---------------------------------------------------------------------------
// CSR build: zero -> histogram -> 3-step exclusive scan -> scatter
// ---------------------------------------------------------------------------
__global__ void zero_kernel(int* __restrict__ deg, int* __restrict__ cur)
{
    int i = blockIdx.x * blockDim.x + threadIdx.x;
    if (i < N_NODES) { deg[i] = 0; cur[i] = 0; }
}

__global__ void hist_kernel(const int* __restrict__ erow, int* __restrict__ deg)
{
    int e = blockIdx.x * blockDim.x + threadIdx.x;
    if (e < N_EDGES) atomicAdd(&deg[erow[e]], 1);
}

__global__ __launch_bounds__(1024) void scan1_kernel(
    const int* __restrict__ deg, int* __restrict__ offset, int* __restrict__ bsum)
{
    __shared__ int buf[2][1024];
    const int t = threadIdx.x;
    const int i = blockIdx.x * 1024 + t;
    const int v = (i < N_NODES) ? deg[i] : 0;
    buf[0][t] = v;
    __syncthreads();
    int src = 0;
#pragma unroll
    for (int d = 1; d < 1024; d <<= 1) {
        int nv = buf[src][t] + (t >= d ? buf[src][t - d] : 0);
        buf[src ^ 1][t] = nv;
        src ^= 1;
        __syncthreads();
    }
    if (i < N_NODES) offset[i] = buf[src][t] - v;
    if (t == 1023)   bsum[blockIdx.x] = buf[src][1023];
}

__global__ __launch_bounds__(128) void scan2_kernel(
    const int* __restrict__ bsum, int* __restrict__ boff, int nb)
{
    __shared__ int buf[2][128];
    const int t = threadIdx.x;
    const int v = (t < nb) ? bsum[t] : 0;
    buf[0][t] = v;
    __syncthreads();
    int src = 0;
#pragma unroll
    for (int d = 1; d < 128; d <<= 1) {
        int nv = buf[src][t] + (t >= d ? buf[src][t - d] : 0);
        buf[src ^ 1][t] = nv;
        src ^= 1;
        __syncthreads();
    }
    boff[t] = buf[src][t] - v;
}

__global__ void scan3_kernel(int* __restrict__ offset, const int* __restrict__ boff)
{
    int i = blockIdx.x * blockDim.x + threadIdx.x;
    if (i < N_NODES) offset[i] += boff[i >> 10];
    if (i == 0) offset[N_NODES] = N_EDGES;
}

__global__ void scatter_kernel(
    const int* __restrict__ erow, const int* __restrict__ ecol,
    const float* __restrict__ eval, const int* __restrict__ offset,
    int* __restrict__ cursor, int2* __restrict__ edges)
{
    int e = blockIdx.x * blockDim.x + threadIdx.x;
    if (e >= N_EDGES) return;
    int r   = erow[e];
    int pos = offset[r] + atomicAdd(&cursor[r], 1);
    edges[pos] = make_int2(ecol[e], __float_as_int(eval[e]));
}

// ---------------------------------------------------------------------------
// Gather: warp per node, lane owns 4 feats (fp16 support); fused bias + ReLU
// ---------------------------------------------------------------------------
__global__ __launch_bounds__(256) void gather_kernel(
    const int* __restrict__ offset, const int2* __restrict__ edges,
    const __half* __restrict__ S, const float* __restrict__ bias,
    float* __restrict__ out)
{
    const int warp = threadIdx.x >> 5;
    const int lane = threadIdx.x & 31;
    const int n    = blockIdx.x * 8 + warp;
    if (n >= N_NODES) return;

    const int start = __ldg(&offset[n]);
    const int end   = __ldg(&offset[n + 1]);

    float4 acc = make_float4(0.f, 0.f, 0.f, 0.f);

    int e0 = start;
    for (; e0 + 32 <= end; e0 += 32) {
        int2 ed = __ldg(&edges[e0 + lane]);
#pragma unroll
        for (int j = 0; j < 32; ++j) {
            int   c = __shfl_sync(0xffffffffu, ed.x, j);
            float v = __int_as_float(__shfl_sync(0xffffffffu, ed.y, j));
            const __half2* sp = (const __half2*)&S[(size_t)c * OUT_F + lane * 4];
            float2 s01 = __half22float2(sp[0]);
            float2 s23 = __half22float2(sp[1]);
            acc.x += s01.x * v; acc.y += s01.y * v;
            acc.z += s23.x * v; acc.w += s23.y * v;
        }
    }
    if (e0 < end) {
        int idx = e0 + lane;
        int2 ed = (idx < end) ? __ldg(&edges[idx]) : make_int2(0, 0);
        int cnt = end - e0;
        for (int j = 0; j < cnt; ++j) {
            int   c = __shfl_sync(0xffffffffu, ed.x, j);
            float v = __int_as_float(__shfl_sync(0xffffffffu, ed.y, j));
            const __half2* sp = (const __half2*)&S[(size_t)c * OUT_F + lane * 4];
            float2 s01 = __half22float2(sp[0]);
            float2 s23 = __half22float2(sp[1]);
            acc.x += s01.x * v; acc.y += s01.y * v;
            acc.z += s23.x * v; acc.w += s23.y * v;
        }
    }

    const float4 b = *(const float4*)&bias[lane * 4];
    float4 o;
    o.x = fmaxf(acc.x + b.x, 0.f);
    o.y = fmaxf(acc.y + b.y, 0.f);
    o.z = fmaxf(acc.z + b.z, 0.f);
    o.w = fmaxf(acc.w + b.w, 0.f);
    *(float4*)&out[(size_t)n * OUT_F + lane * 4] = o;
}

// ---------------------------------------------------------------------------
// Inputs (metadata order): x, edge_row, edge_col, edge_val, weight, bias
// GEMM chain forked onto a side stream, overlapped with CSR build; joined
// before gather. Stream/event create+destroy are host-side (capture-time only).
// ---------------------------------------------------------------------------
extern "C" void kernel_launch(void* const* d_in, const int* in_sizes, int n_in,
                              void* d_out, int out_size)
{
    const float* x     = (const float*)d_in[0];
    const int*   erow  = (const int*)  d_in[1];
    const int*   ecol  = (const int*)  d_in[2];
    const float* eval_ = (const float*)d_in[3];
    const float* w     = (const float*)d_in[4];
    const float* bias  = (const float*)d_in[5];
    float*       out   = (float*)d_out;

    __half* support; cudaGetSymbolAddress((void**)&support, g_support);
    int2*  edges;    cudaGetSymbolAddress((void**)&edges,   g_edges);
    int*   deg;      cudaGetSymbolAddress((void**)&deg,     g_deg);
    int*   cursor;   cudaGetSymbolAddress((void**)&cursor,  g_cursor);
    int*   offset;   cudaGetSymbolAddress((void**)&offset,  g_offset);
    int*   bsum;     cudaGetSymbolAddress((void**)&bsum,    g_bsum);
    int*   boff;     cudaGetSymbolAddress((void**)&boff,    g_boff);
    __half* bh;      cudaGetSymbolAddress((void**)&bh,      g_Bh);

    const int nb = (N_NODES + 1023) / 1024;

    cudaStream_t s2;
    cudaEvent_t  eFork, eJoin;
    cudaStreamCreateWithFlags(&s2, cudaStreamNonBlocking);
    cudaEventCreateWithFlags(&eFork, cudaEventDisableTiming);
    cudaEventCreateWithFlags(&eJoin, cudaEventDisableTiming);

    // ---- fork: GEMM chain on s2 ----
    cudaEventRecord(eFork, 0);
    cudaStreamWaitEvent(s2, eFork, 0);
    wconv_kernel<<<(IN_F * OUT_F + 255) / 256, 256, 0, s2>>>(w, bh);
    gemm_mma_kernel<<<(N_NODES + 127) / 128, 256, 0, s2>>>(x, bh, support);
    cudaEventRecord(eJoin, s2);

    // ---- CSR build on the main (capture) stream, concurrent with GEMM ----
    zero_kernel<<<(N_NODES + 255) / 256, 256>>>(deg, cursor);
    hist_kernel<<<(N_EDGES + 255) / 256, 256>>>(erow, deg);
    scan1_kernel<<<nb, 1024>>>(deg, offset, bsum);
    scan2_kernel<<<1, 128>>>(bsum, boff, nb);
    scan3_kernel<<<(N_NODES + 255) / 256, 256>>>(offset, boff);
    scatter_kernel<<<(N_EDGES + 255) / 256, 256>>>(erow, ecol, eval_, offset, cursor, edges);

    // ---- join, then gather ----
    cudaStreamWaitEvent(0, eJoin, 0);
    gather_kernel<<<(N_NODES + 7) / 8, 256>>>(offset, edges, support, bias, out);

    cudaEventDestroy(eFork);
    cudaEventDestroy(eJoin);
    cudaStreamDestroy(s2);
}

// round 11
// speedup vs baseline: 3.6000x; 1.0115x over previous
#include <cuda_runtime.h>
#include <cuda_fp16.h>
#include <cstdint>

#define N_NODES 100000
#define N_EDGES 3200000
#define IN_F    256
#define OUT_F   128

// -------- device scratch (no allocs allowed) --------
__device__ __half g_support[(size_t)N_NODES * OUT_F];  // X @ W in fp16
__device__ int2  g_edges[N_EDGES];                     // (col, val-bits) grouped by row
__device__ int   g_rank[N_EDGES];                      // edge rank within its row
__device__ int   g_deg[N_NODES];
__device__ int   g_offset[N_NODES + 1];
__device__ int   g_bsum[128];
__device__ int   g_boff[128];
// W in fp16, transposed to [n][k] (k contiguous) for mma B-col fragments
__device__ __align__(16) __half g_Bh[OUT_F * IN_F];

// ---------------------------------------------------------------------------
// W -> fp16, transposed [n][k]
// ---------------------------------------------------------------------------
__global__ void wconv_kernel(const float* __restrict__ W,
                             __half* __restrict__ Bh)
{
    int idx = blockIdx.x * blockDim.x + threadIdx.x;   // k*128 + n
    if (idx >= IN_F * OUT_F) return;
    int k = idx >> 7;
    int n = idx & 127;
    Bh[n * IN_F + k] = __float2half_rn(W[idx]);
}

// ---------------------------------------------------------------------------
// fp16 GEMM via mma.sync m16n8k16 (f32 accum); fp16 output for the gather
// ---------------------------------------------------------------------------
#define ASTRIDE 72          // padded row stride (elements) for A/B smem tiles

__device__ __forceinline__ void mma_f16(float* c, const uint32_t* a, const uint32_t* b)
{
    asm volatile(
        "mma.sync.aligned.m16n8k16.row.col.f32.f16.f16.f32 "
        "{%0,%1,%2,%3}, {%4,%5,%6,%7}, {%8,%9}, {%0,%1,%2,%3};\n"
        : "+f"(c[0]), "+f"(c[1]), "+f"(c[2]), "+f"(c[3])
        : "r"(a[0]), "r"(a[1]), "r"(a[2]), "r"(a[3]), "r"(b[0]), "r"(b[1]));
}

__global__ __launch_bounds__(256) void gemm_mma_kernel(
    const float* __restrict__ X,
    const __half* __restrict__ Bhg,
    __half* __restrict__ S)
{
    __shared__ __align__(16) __half Ah[128 * ASTRIDE];
    __shared__ __align__(16) __half Bh[128 * ASTRIDE];

    const int tid  = threadIdx.x;
    const int wid  = tid >> 5;
    const int lane = tid & 31;
    const int g    = lane >> 2;
    const int tig  = lane & 3;
    const int row0 = blockIdx.x * 128;

    const int mrow0 = (wid & 3) * 32;
    const int ncol0 = (wid >> 2) * 64;

    float acc[2][8][4];
#pragma unroll
    for (int mi = 0; mi < 2; ++mi)
#pragma unroll
        for (int ni = 0; ni < 8; ++ni)
#pragma unroll
            for (int r = 0; r < 4; ++r) acc[mi][ni][r] = 0.f;

    for (int k0 = 0; k0 < IN_F; k0 += 64) {
        if (k0) __syncthreads();

#pragma unroll
        for (int i = 0; i < 8; ++i) {
            int idx = tid + i * 256;
            int row = idx >> 4;
            int c4  = (idx & 15) * 4;
            float4 v = make_float4(0.f, 0.f, 0.f, 0.f);
            int grow = row0 + row;
            if (grow < N_NODES)
                v = *(const float4*)&X[(size_t)grow * IN_F + k0 + c4];
            int off = row * ASTRIDE + c4;
            *(__half2*)&Ah[off]     = __floats2half2_rn(v.x, v.y);
            *(__half2*)&Ah[off + 2] = __floats2half2_rn(v.z, v.w);
        }
#pragma unroll
        for (int i = 0; i < 4; ++i) {
            int idx = tid + i * 256;
            int n   = idx >> 3;
            int k8  = (idx & 7) * 8;
            uint4 vh = *(const uint4*)&Bhg[n * IN_F + k0 + k8];
            *(uint4*)&Bh[n * ASTRIDE + k8] = vh;
        }
        __syncthreads();

#pragma unroll
        for (int kk = 0; kk < 4; ++kk) {
            const int kb = kk * 16;
            uint32_t ah[2][4];
#pragma unroll
            for (int mi = 0; mi < 2; ++mi) {
                int ra = (mrow0 + mi * 16 + g) * ASTRIDE + kb + 2 * tig;
                int rb = ra + 8 * ASTRIDE;
                ah[mi][0] = *(const uint32_t*)&Ah[ra];
                ah[mi][1] = *(const uint32_t*)&Ah[rb];
                ah[mi][2] = *(const uint32_t*)&Ah[ra + 8];
                ah[mi][3] = *(const uint32_t*)&Ah[rb + 8];
            }
#pragma unroll
            for (int ni = 0; ni < 8; ++ni) {
                int cb = (ncol0 + ni * 8 + g) * ASTRIDE + kb + 2 * tig;
                uint32_t bh[2];
                bh[0] = *(const uint32_t*)&Bh[cb];
                bh[1] = *(const uint32_t*)&Bh[cb + 8];
#pragma unroll
                for (int mi = 0; mi < 2; ++mi)
                    mma_f16(acc[mi][ni], ah[mi], bh);
            }
        }
    }

#pragma unroll
    for (int mi = 0; mi < 2; ++mi) {
        int r0 = row0 + mrow0 + mi * 16 + g;
        int r1 = r0 + 8;
#pragma unroll
        for (int ni = 0; ni < 8; ++ni) {
            int col = ncol0 + ni * 8 + tig * 2;
            if (r0 < N_NODES)
                *(__half2*)&S[(size_t)r0 * OUT_F + col] =
                    __floats2half2_rn(acc[mi][ni][0], acc[mi][ni][1]);
            if (r1 < N_NODES)
                *(__half2*)&S[(size_t)r1 * OUT_F + col] =
                    __floats2half2_rn(acc[mi][ni][2], acc[mi][ni][3]);
        }
    }
}

// ---------------------------------------------------------------------------
// CSR build: zero -> hist(+rank) -> 3-step exclusive scan -> atomic-free scatter
// ---------------------------------------------------------------------------
__global__ void zero_kernel(int* __restrict__ deg)
{
    int i = blockIdx.x * blockDim.x + threadIdx.x;
    if (i < N_NODES) deg[i] = 0;
}

__global__ void hist_kernel(const int* __restrict__ erow, int* __restrict__ deg,
                            int* __restrict__ rank)
{
    int e = blockIdx.x * blockDim.x + threadIdx.x;
    if (e < N_EDGES) rank[e] = atomicAdd(&deg[erow[e]], 1);
}

__global__ __launch_bounds__(1024) void scan1_kernel(
    const int* __restrict__ deg, int* __restrict__ offset, int* __restrict__ bsum)
{
    __shared__ int buf[2][1024];
    const int t = threadIdx.x;
    const int i = blockIdx.x * 1024 + t;
    const int v = (i < N_NODES) ? deg[i] : 0;
    buf[0][t] = v;
    __syncthreads();
    int src = 0;
#pragma unroll
    for (int d = 1; d < 1024; d <<= 1) {
        int nv = buf[src][t] + (t >= d ? buf[src][t - d] : 0);
        buf[src ^ 1][t] = nv;
        src ^= 1;
        __syncthreads();
    }
    if (i < N_NODES) offset[i] = buf[src][t] - v;
    if (t == 1023)   bsum[blockIdx.x] = buf[src][1023];
}

__global__ __launch_bounds__(128) void scan2_kernel(
    const int* __restrict__ bsum, int* __restrict__ boff, int nb)
{
    __shared__ int buf[2][128];
    const int t = threadIdx.x;
    const int v = (t < nb) ? bsum[t] : 0;
    buf[0][t] = v;
    __syncthreads();
    int src = 0;
#pragma unroll
    for (int d = 1; d < 128; d <<= 1) {
        int nv = buf[src][t] + (t >= d ? buf[src][t - d] : 0);
        buf[src ^ 1][t] = nv;
        src ^= 1;
        __syncthreads();
    }
    boff[t] = buf[src][t] - v;
}

__global__ void scan3_kernel(int* __restrict__ offset, const int* __restrict__ boff)
{
    int i = blockIdx.x * blockDim.x + threadIdx.x;
    if (i < N_NODES) offset[i] += boff[i >> 10];
    if (i == 0) offset[N_NODES] = N_EDGES;
}

__global__ void scatter_kernel(
    const int* __restrict__ erow, const int* __restrict__ ecol,
    const float* __restrict__ eval, const int* __restrict__ offset,
    const int* __restrict__ rank, int2* __restrict__ edges)
{
    int e = blockIdx.x * blockDim.x + threadIdx.x;
    if (e >= N_EDGES) return;
    int pos = offset[erow[e]] + rank[e];
    edges[pos] = make_int2(ecol[e], __float_as_int(eval[e]));
}

// ---------------------------------------------------------------------------
// Gather: warp per node, lane owns 4 feats (fp16 support); fused bias + ReLU
// ---------------------------------------------------------------------------
__global__ __launch_bounds__(256) void gather_kernel(
    const int* __restrict__ offset, const int2* __restrict__ edges,
    const __half* __restrict__ S, const float* __restrict__ bias,
    float* __restrict__ out)
{
    const int warp = threadIdx.x >> 5;
    const int lane = threadIdx.x & 31;
    const int n    = blockIdx.x * 8 + warp;
    if (n >= N_NODES) return;

    const int start = __ldg(&offset[n]);
    const int end   = __ldg(&offset[n + 1]);

    float4 acc = make_float4(0.f, 0.f, 0.f, 0.f);

    int e0 = start;
    for (; e0 + 32 <= end; e0 += 32) {
        int2 ed = __ldg(&edges[e0 + lane]);
#pragma unroll
        for (int j = 0; j < 32; ++j) {
            int   c = __shfl_sync(0xffffffffu, ed.x, j);
            float v = __int_as_float(__shfl_sync(0xffffffffu, ed.y, j));
            const __half2* sp = (const __half2*)&S[(size_t)c * OUT_F + lane * 4];
            float2 s01 = __half22float2(sp[0]);
            float2 s23 = __half22float2(sp[1]);
            acc.x += s01.x * v; acc.y += s01.y * v;
            acc.z += s23.x * v; acc.w += s23.y * v;
        }
    }
    if (e0 < end) {
        int idx = e0 + lane;
        int2 ed = (idx < end) ? __ldg(&edges[idx]) : make_int2(0, 0);
        int cnt = end - e0;
        for (int j = 0; j < cnt; ++j) {
            int   c = __shfl_sync(0xffffffffu, ed.x, j);
            float v = __int_as_float(__shfl_sync(0xffffffffu, ed.y, j));
            const __half2* sp = (const __half2*)&S[(size_t)c * OUT_F + lane * 4];
            float2 s01 = __half22float2(sp[0]);
            float2 s23 = __half22float2(sp[1]);
            acc.x += s01.x * v; acc.y += s01.y * v;
            acc.z += s23.x * v; acc.w += s23.y * v;
        }
    }

    const float4 b = *(const float4*)&bias[lane * 4];
    float4 o;
    o.x = fmaxf(acc.x + b.x, 0.f);
    o.y = fmaxf(acc.y + b.y, 0.f);
    o.z = fmaxf(acc.z + b.z, 0.f);
    o.w = fmaxf(acc.w + b.w, 0.f);
    *(float4*)&out[(size_t)n * OUT_F + lane * 4] = o;
}

// ---------------------------------------------------------------------------
// Inputs (metadata order): x, edge_row, edge_col, edge_val, weight, bias
// GEMM chain forked onto a side stream; CSR build on main stream; join at gather.
// ---------------------------------------------------------------------------
extern "C" void kernel_launch(void* const* d_in, const int* in_sizes, int n_in,
                              void* d_out, int out_size)
{
    const float* x     = (const float*)d_in[0];
    const int*   erow  = (const int*)  d_in[1];
    const int*   ecol  = (const int*)  d_in[2];
    const float* eval_ = (const float*)d_in[3];
    const float* w     = (const float*)d_in[4];
    const float* bias  = (const float*)d_in[5];
    float*       out   = (float*)d_out;

    __half* support; cudaGetSymbolAddress((void**)&support, g_support);
    int2*  edges;    cudaGetSymbolAddress((void**)&edges,   g_edges);
    int*   rank;     cudaGetSymbolAddress((void**)&rank,    g_rank);
    int*   deg;      cudaGetSymbolAddress((void**)&deg,     g_deg);
    int*   offset;   cudaGetSymbolAddress((void**)&offset,  g_offset);
    int*   bsum;     cudaGetSymbolAddress((void**)&bsum,    g_bsum);
    int*   boff;     cudaGetSymbolAddress((void**)&boff,    g_boff);
    __half* bh;      cudaGetSymbolAddress((void**)&bh,      g_Bh);

    const int nb = (N_NODES + 1023) / 1024;

    cudaStream_t s2;
    cudaEvent_t  eFork, eJoin;
    cudaStreamCreateWithFlags(&s2, cudaStreamNonBlocking);
    cudaEventCreateWithFlags(&eFork, cudaEventDisableTiming);
    cudaEventCreateWithFlags(&eJoin, cudaEventDisableTiming);

    // ---- fork: GEMM chain on s2 ----
    cudaEventRecord(eFork, 0);
    cudaStreamWaitEvent(s2, eFork, 0);
    wconv_kernel<<<(IN_F * OUT_F + 255) / 256, 256, 0, s2>>>(w, bh);
    gemm_mma_kernel<<<(N_NODES + 127) / 128, 256, 0, s2>>>(x, bh, support);
    cudaEventRecord(eJoin, s2);

    // ---- CSR build on the main (capture) stream ----
    zero_kernel<<<(N_NODES + 255) / 256, 256>>>(deg);
    hist_kernel<<<(N_EDGES + 255) / 256, 256>>>(erow, deg, rank);
    scan1_kernel<<<nb, 1024>>>(deg, offset, bsum);
    scan2_kernel<<<1, 128>>>(bsum, boff, nb);
    scan3_kernel<<<(N_NODES + 255) / 256, 256>>>(offset, boff);
    scatter_kernel<<<(N_EDGES + 255) / 256, 256>>>(erow, ecol, eval_, offset, rank, edges);

    // ---- join, then gather ----
    cudaStreamWaitEvent(0, eJoin, 0);
    gather_kernel<<<(N_NODES + 7) / 8, 256>>>(offset, edges, support, bias, out);

    cudaEventDestroy(eFork);
    cudaEventDestroy(eJoin);
    cudaStreamDestroy(s2);
}

// round 13
// speedup vs baseline: 3.7433x; 1.0398x over previous
#include <cuda_runtime.h>
#include <cuda_fp16.h>
#include <cstdint>

#define N_NODES 100000
#define N_EDGES 3200000
#define IN_F    256
#define OUT_F   128
#define SCAN_NB ((N_NODES + 1023) / 1024)   // 98

// -------- device scratch (no allocs allowed) --------
__device__ __half g_support[(size_t)N_NODES * OUT_F];  // X @ W in fp16
__device__ unsigned int g_edges[N_EDGES];              // packed (val15 << 17 | col17), grouped by row
__device__ int   g_rank[N_EDGES];                      // edge rank within its row
__device__ int   g_deg[N_NODES];
__device__ int   g_offset[N_NODES + 1];
__device__ int   g_blk[128];                           // lookback state: (sum<<2)|status
// W in fp16, transposed to [n][k] (k contiguous) for mma B-col fragments
__device__ __align__(16) __half g_Bh[OUT_F * IN_F];

// ---------------------------------------------------------------------------
// W -> fp16, transposed [n][k]
// ---------------------------------------------------------------------------
__global__ void wconv_kernel(const float* __restrict__ W,
                             __half* __restrict__ Bh)
{
    int idx = blockIdx.x * blockDim.x + threadIdx.x;   // k*128 + n
    if (idx >= IN_F * OUT_F) return;
    int k = idx >> 7;
    int n = idx & 127;
    Bh[n * IN_F + k] = __float2half_rn(W[idx]);
}

// ---------------------------------------------------------------------------
// fp16 GEMM via mma.sync m16n8k16 (f32 accum); fp16 output for the gather
// ---------------------------------------------------------------------------
#define ASTRIDE 72          // padded row stride (elements) for A/B smem tiles

__device__ __forceinline__ void mma_f16(float* c, const uint32_t* a, const uint32_t* b)
{
    asm volatile(
        "mma.sync.aligned.m16n8k16.row.col.f32.f16.f16.f32 "
        "{%0,%1,%2,%3}, {%4,%5,%6,%7}, {%8,%9}, {%0,%1,%2,%3};\n"
        : "+f"(c[0]), "+f"(c[1]), "+f"(c[2]), "+f"(c[3])
        : "r"(a[0]), "r"(a[1]), "r"(a[2]), "r"(a[3]), "r"(b[0]), "r"(b[1]));
}

__global__ __launch_bounds__(256) void gemm_mma_kernel(
    const float* __restrict__ X,
    const __half* __restrict__ Bhg,
    __half* __restrict__ S)
{
    __shared__ __align__(16) __half Ah[128 * ASTRIDE];
    __shared__ __align__(16) __half Bh[128 * ASTRIDE];

    const int tid  = threadIdx.x;
    const int wid  = tid >> 5;
    const int lane = tid & 31;
    const int g    = lane >> 2;
    const int tig  = lane & 3;
    const int row0 = blockIdx.x * 128;

    const int mrow0 = (wid & 3) * 32;
    const int ncol0 = (wid >> 2) * 64;

    float acc[2][8][4];
#pragma unroll
    for (int mi = 0; mi < 2; ++mi)
#pragma unroll
        for (int ni = 0; ni < 8; ++ni)
#pragma unroll
            for (int r = 0; r < 4; ++r) acc[mi][ni][r] = 0.f;

    for (int k0 = 0; k0 < IN_F; k0 += 64) {
        if (k0) __syncthreads();

#pragma unroll
        for (int i = 0; i < 8; ++i) {
            int idx = tid + i * 256;
            int row = idx >> 4;
            int c4  = (idx & 15) * 4;
            float4 v = make_float4(0.f, 0.f, 0.f, 0.f);
            int grow = row0 + row;
            if (grow < N_NODES)
                v = *(const float4*)&X[(size_t)grow * IN_F + k0 + c4];
            int off = row * ASTRIDE + c4;
            *(__half2*)&Ah[off]     = __floats2half2_rn(v.x, v.y);
            *(__half2*)&Ah[off + 2] = __floats2half2_rn(v.z, v.w);
        }
#pragma unroll
        for (int i = 0; i < 4; ++i) {
            int idx = tid + i * 256;
            int n   = idx >> 3;
            int k8  = (idx & 7) * 8;
            uint4 vh = *(const uint4*)&Bhg[n * IN_F + k0 + k8];
            *(uint4*)&Bh[n * ASTRIDE + k8] = vh;
        }
        __syncthreads();

#pragma unroll
        for (int kk = 0; kk < 4; ++kk) {
            const int kb = kk * 16;
            uint32_t ah[2][4];
#pragma unroll
            for (int mi = 0; mi < 2; ++mi) {
                int ra = (mrow0 + mi * 16 + g) * ASTRIDE + kb + 2 * tig;
                int rb = ra + 8 * ASTRIDE;
                ah[mi][0] = *(const uint32_t*)&Ah[ra];
                ah[mi][1] = *(const uint32_t*)&Ah[rb];
                ah[mi][2] = *(const uint32_t*)&Ah[ra + 8];
                ah[mi][3] = *(const uint32_t*)&Ah[rb + 8];
            }
#pragma unroll
            for (int ni = 0; ni < 8; ++ni) {
                int cb = (ncol0 + ni * 8 + g) * ASTRIDE + kb + 2 * tig;
                uint32_t bh[2];
                bh[0] = *(const uint32_t*)&Bh[cb];
                bh[1] = *(const uint32_t*)&Bh[cb + 8];
#pragma unroll
                for (int mi = 0; mi < 2; ++mi)
                    mma_f16(acc[mi][ni], ah[mi], bh);
            }
        }
    }

#pragma unroll
    for (int mi = 0; mi < 2; ++mi) {
        int r0 = row0 + mrow0 + mi * 16 + g;
        int r1 = r0 + 8;
#pragma unroll
        for (int ni = 0; ni < 8; ++ni) {
            int col = ncol0 + ni * 8 + tig * 2;
            if (r0 < N_NODES)
                *(__half2*)&S[(size_t)r0 * OUT_F + col] =
                    __floats2half2_rn(acc[mi][ni][0], acc[mi][ni][1]);
            if (r1 < N_NODES)
                *(__half2*)&S[(size_t)r1 * OUT_F + col] =
                    __floats2half2_rn(acc[mi][ni][2], acc[mi][ni][3]);
        }
    }
}

// ---------------------------------------------------------------------------
// CSR build: zero -> hist(+rank) -> fused lookback scan -> atomic-free scatter
// ---------------------------------------------------------------------------
__global__ void zero_kernel(int* __restrict__ deg, int* __restrict__ blk)
{
    int i = blockIdx.x * blockDim.x + threadIdx.x;
    if (i < N_NODES) deg[i] = 0;
    if (i < 128) blk[i] = 0;
}

__global__ void hist_kernel(const int* __restrict__ erow, int* __restrict__ deg,
                            int* __restrict__ rank)
{
    int e = blockIdx.x * blockDim.x + threadIdx.x;
    if (e < N_EDGES) rank[e] = atomicAdd(&deg[erow[e]], 1);
}

// Single-kernel exclusive scan over deg -> offset (decoupled lookback).
// All SCAN_NB=98 blocks are co-resident (148 SMs), so the spin is safe.
// blk[b] = (sum << 2) | status; status 0=invalid, 1=aggregate, 2=inclusive.
__global__ __launch_bounds__(1024) void scan_fused_kernel(
    const int* __restrict__ deg, int* __restrict__ offset, int* __restrict__ blk)
{
    __shared__ int buf[2][1024];
    __shared__ int base_sh;
    const int t   = threadIdx.x;
    const int bid = blockIdx.x;
    const int i   = bid * 1024 + t;
    const int v   = (i < N_NODES) ? deg[i] : 0;
    buf[0][t] = v;
    __syncthreads();
    int src = 0;
#pragma unroll
    for (int d = 1; d < 1024; d <<= 1) {
        int nv = buf[src][t] + (t >= d ? buf[src][t - d] : 0);
        buf[src ^ 1][t] = nv;
        src ^= 1;
        __syncthreads();
    }
    const int incl  = buf[src][t];      // inclusive prefix within block
    const int total = buf[src][1023];   // block aggregate (< 2^22, fits <<2)

    if (t == 0) {
        if (bid == 0) {
            atomicExch(&blk[0], (total << 2) | 2);
            base_sh = 0;
        } else {
            atomicExch(&blk[bid], (total << 2) | 1);
            int base = 0;
            int p = bid - 1;
            while (true) {
                int s = atomicAdd(&blk[p], 0);   // atomic read (coherent)
                int st = s & 3;
                if (st == 0) continue;           // predecessor not published yet
                base += s >> 2;
                if (st == 2) break;              // inclusive: done
                --p;                             // aggregate: keep looking back
            }
            atomicExch(&blk[bid], ((base + total) << 2) | 2);
            base_sh = base;
        }
    }
    __syncthreads();
    const int base = base_sh;
    if (i < N_NODES) offset[i] = base + incl - v;   // exclusive prefix
    if (bid == 0 && t == 0) offset[N_NODES] = N_EDGES;
}

// Atomic-free scatter; packs (col, fp16 val sans sign bit) into 4 bytes.
// edge_val >= 0 always, so the fp16 sign bit is 0 and 15 bits suffice.
__global__ void scatter_kernel(
    const int* __restrict__ erow, const int* __restrict__ ecol,
    const float* __restrict__ eval, const int* __restrict__ offset,
    const int* __restrict__ rank, unsigned int* __restrict__ edges)
{
    int e = blockIdx.x * blockDim.x + threadIdx.x;
    if (e >= N_EDGES) return;
    int pos = offset[erow[e]] + rank[e];
    unsigned int hb = (unsigned int)__half_as_ushort(__float2half_rn(eval[e]));
    edges[pos] = (hb << 17) | (unsigned int)ecol[e];
}

// ---------------------------------------------------------------------------
// Gather: warp per node, lane owns 4 feats (fp16 support); fused bias + ReLU
// ---------------------------------------------------------------------------
__global__ __launch_bounds__(256) void gather_kernel(
    const int* __restrict__ offset, const unsigned int* __restrict__ edges,
    const __half* __restrict__ S, const float* __restrict__ bias,
    float* __restrict__ out)
{
    const int warp = threadIdx.x >> 5;
    const int lane = threadIdx.x & 31;
    const int n    = blockIdx.x * 8 + warp;
    if (n >= N_NODES) return;

    const int start = __ldg(&offset[n]);
    const int end   = __ldg(&offset[n + 1]);

    float4 acc = make_float4(0.f, 0.f, 0.f, 0.f);

    int e0 = start;
    for (; e0 + 32 <= end; e0 += 32) {
        unsigned int ed = __ldg(&edges[e0 + lane]);
#pragma unroll
        for (int j = 0; j < 32; ++j) {
            unsigned int p = __shfl_sync(0xffffffffu, ed, j);
            int   c = (int)(p & 0x1FFFFu);
            float v = __half2float(__ushort_as_half((unsigned short)(p >> 17)));
            const __half2* sp = (const __half2*)&S[(size_t)c * OUT_F + lane * 4];
            float2 s01 = __half22float2(sp[0]);
            float2 s23 = __half22float2(sp[1]);
            acc.x += s01.x * v; acc.y += s01.y * v;
            acc.z += s23.x * v; acc.w += s23.y * v;
        }
    }
    if (e0 < end) {
        int idx = e0 + lane;
        unsigned int ed = (idx < end) ? __ldg(&edges[idx]) : 0u;
        int cnt = end - e0;
        for (int j = 0; j < cnt; ++j) {
            unsigned int p = __shfl_sync(0xffffffffu, ed, j);
            int   c = (int)(p & 0x1FFFFu);
            float v = __half2float(__ushort_as_half((unsigned short)(p >> 17)));
            const __half2* sp = (const __half2*)&S[(size_t)c * OUT_F + lane * 4];
            float2 s01 = __half22float2(sp[0]);
            float2 s23 = __half22float2(sp[1]);
            acc.x += s01.x * v; acc.y += s01.y * v;
            acc.z += s23.x * v; acc.w += s23.y * v;
        }
    }

    const float4 b = *(const float4*)&bias[lane * 4];
    float4 o;
    o.x = fmaxf(acc.x + b.x, 0.f);
    o.y = fmaxf(acc.y + b.y, 0.f);
    o.z = fmaxf(acc.z + b.z, 0.f);
    o.w = fmaxf(acc.w + b.w, 0.f);
    *(float4*)&out[(size_t)n * OUT_F + lane * 4] = o;
}

// ---------------------------------------------------------------------------
// Inputs (metadata order): x, edge_row, edge_col, edge_val, weight, bias
// GEMM chain forked onto a side stream; CSR build on main stream; join at gather.
// ---------------------------------------------------------------------------
extern "C" void kernel_launch(void* const* d_in, const int* in_sizes, int n_in,
                              void* d_out, int out_size)
{
    const float* x     = (const float*)d_in[0];
    const int*   erow  = (const int*)  d_in[1];
    const int*   ecol  = (const int*)  d_in[2];
    const float* eval_ = (const float*)d_in[3];
    const float* w     = (const float*)d_in[4];
    const float* bias  = (const float*)d_in[5];
    float*       out   = (float*)d_out;

    __half* support;     cudaGetSymbolAddress((void**)&support, g_support);
    unsigned int* edges; cudaGetSymbolAddress((void**)&edges,   g_edges);
    int*   rank;         cudaGetSymbolAddress((void**)&rank,    g_rank);
    int*   deg;          cudaGetSymbolAddress((void**)&deg,     g_deg);
    int*   offset;       cudaGetSymbolAddress((void**)&offset,  g_offset);
    int*   blk;          cudaGetSymbolAddress((void**)&blk,     g_blk);
    __half* bh;          cudaGetSymbolAddress((void**)&bh,      g_Bh);

    cudaStream_t s2;
    cudaEvent_t  eFork, eJoin;
    cudaStreamCreateWithFlags(&s2, cudaStreamNonBlocking);
    cudaEventCreateWithFlags(&eFork, cudaEventDisableTiming);
    cudaEventCreateWithFlags(&eJoin, cudaEventDisableTiming);

    // ---- fork: GEMM chain on s2 ----
    cudaEventRecord(eFork, 0);
    cudaStreamWaitEvent(s2, eFork, 0);
    wconv_kernel<<<(IN_F * OUT_F + 255) / 256, 256, 0, s2>>>(w, bh);
    gemm_mma_kernel<<<(N_NODES + 127) / 128, 256, 0, s2>>>(x, bh, support);
    cudaEventRecord(eJoin, s2);

    // ---- CSR build on the main (capture) stream ----
    zero_kernel<<<(N_NODES + 255) / 256, 256>>>(deg, blk);
    hist_kernel<<<(N_EDGES + 255) / 256, 256>>>(erow, deg, rank);
    scan_fused_kernel<<<SCAN_NB, 1024>>>(deg, offset, blk);
    scatter_kernel<<<(N_EDGES + 255) / 256, 256>>>(erow, ecol, eval_, offset, rank, edges);

    // ---- join, then gather ----
    cudaStreamWaitEvent(0, eJoin, 0);
    gather_kernel<<<(N_NODES + 7) / 8, 256>>>(offset, edges, support, bias, out);

    cudaEventDestroy(eFork);
    cudaEventDestroy(eJoin);
    cudaStreamDestroy(s2);
}